// round 10
// baseline (speedup 1.0000x reference)
#include <cuda_runtime.h>
#include <cuda_bf16.h>
#include <cuda_fp16.h>
#include <stdint.h>
#include <math.h>

// Problem constants (fixed by the reference)
#define F_IN   512
#define F_HID  256
#define F_OUT  40
#define MAXN   100000
#define MAXE   3200000

// ---------------- scratch (device globals; no runtime allocation) ----------------
__device__ int   g_is32;
__device__ int   g_deg[MAXN];
__device__ int   g_cnt[MAXN];
__device__ float g_dinv[MAXN];
__device__ int   g_rowptr[MAXN + 1];
__device__ int   g_cursor[MAXN];
__device__ int   g_adj[MAXE];
__device__ int   g_part[256];
__device__ float g_w2t[F_OUT * F_HID];
__device__ unsigned g_w1p[(F_IN / 2) * F_HID];    // W1 packed half2 along k: [k2][n]
__device__ unsigned g_hh[(long)MAXN * (F_HID/2)]; // h_s half2-packed (dinv*x@W1)
__device__ unsigned g_h2h[(long)MAXN * (F_OUT/2)];// h2_s half2-packed (dinv*relu@W2)

// ---------------- helpers ----------------
__device__ __forceinline__ unsigned packh2(float lo, float hi) {
    __half2 h = __floats2half2_rn(lo, hi);
    return *(unsigned*)&h;
}
__device__ __forceinline__ int decode_idx(const void* raw, int is32, long e, int n) {
    long long v = is32 ? (long long)((const int*)raw)[e] : ((const long long*)raw)[e];
    if (v < 0) v = 0;
    if (v >= n) v = n - 1;
    return (int)v;
}

// ---------------- init / dtype detect ----------------
__global__ void k_init(int n) {
    int i = blockIdx.x * blockDim.x + threadIdx.x;
    if (i < n) { g_deg[i] = 1; g_cnt[i] = 0; }
    if (i == 0) g_is32 = 0;
}

// Sample first 64K int64 words: any out-of-range value => data is really int32.
__global__ void k_detect(const long long* __restrict__ ei, int E, int n) {
    int cnt = min(E, 1 << 16);
    int bad = 0;
    for (int e = blockIdx.x * blockDim.x + threadIdx.x; e < cnt; e += gridDim.x * blockDim.x) {
        long long v = ei[e];
        if (v < 0 || v >= n) bad = 1;
    }
    if (__syncthreads_or(bad)) {
        if (threadIdx.x == 0) g_is32 = 1;
    }
}

// ---------------- histogram straight from raw buffer ----------------
__global__ void k_hist(const void* __restrict__ raw, int E, int n) {
    int is32 = g_is32;
    for (long e = blockIdx.x * blockDim.x + threadIdx.x; e < 2L * E; e += (long)gridDim.x * blockDim.x) {
        int vi = decode_idx(raw, is32, e, n);
        if (e < E) atomicAdd(&g_cnt[vi], 1);   // row counts
        else       atomicAdd(&g_deg[vi], 1);   // col degrees
    }
}

__global__ void k_dinv(int n) {
    int i = blockIdx.x * blockDim.x + threadIdx.x;
    if (i < n) g_dinv[i] = rsqrtf((float)g_deg[i]);
}

// ---------------- CSR build ----------------
__global__ void k_scan1(int n) {
    __shared__ int s[1024];
    int tid = threadIdx.x;
    int idx = blockIdx.x * 1024 + tid;
    int v = (idx < n) ? g_cnt[idx] : 0;
    s[tid] = v;
    __syncthreads();
    for (int off = 1; off < 1024; off <<= 1) {
        int t = (tid >= off) ? s[tid - off] : 0;
        __syncthreads();
        s[tid] += t;
        __syncthreads();
    }
    if (idx < n) g_rowptr[idx] = s[tid] - v;
    if (tid == 1023) g_part[blockIdx.x] = s[1023];
}

__global__ void k_scan2(int nb) {
    __shared__ int s[256];
    int tid = threadIdx.x;
    int v = (tid < nb) ? g_part[tid] : 0;
    s[tid] = v;
    __syncthreads();
    for (int off = 1; off < 256; off <<= 1) {
        int t = (tid >= off) ? s[tid - off] : 0;
        __syncthreads();
        s[tid] += t;
        __syncthreads();
    }
    if (tid < nb) g_part[tid] = s[tid] - v;
}

__global__ void k_scan3(int n, int E) {
    int i = blockIdx.x * blockDim.x + threadIdx.x;
    if (i < n) {
        int rp = g_rowptr[i] + g_part[i >> 10];
        g_rowptr[i] = rp;
        g_cursor[i] = rp;
    }
    if (blockIdx.x == 0 && threadIdx.x == 0) g_rowptr[n] = E;
}

__global__ void k_fill(const void* __restrict__ raw, int E, int n) {
    int is32 = g_is32;
    for (int e = blockIdx.x * blockDim.x + threadIdx.x; e < E; e += gridDim.x * blockDim.x) {
        int r = decode_idx(raw, is32, e, n);
        int c = decode_idx(raw, is32, (long)E + e, n);
        int pos = atomicAdd(&g_cursor[r], 1);
        g_adj[pos] = c;
    }
}

// ---------------- weight prep ----------------
__global__ void k_tw2(const float* __restrict__ W2) {
    int idx = blockIdx.x * blockDim.x + threadIdx.x;
    if (idx < F_OUT * F_HID) {
        int o = idx / F_HID, f = idx % F_HID;
        g_w2t[idx] = W2[f * F_OUT + o];
    }
}

// W1 [512][256] fp32 -> packed half2 along k
__global__ void k_tw1p(const float* __restrict__ W1) {
    int idx = blockIdx.x * blockDim.x + threadIdx.x;
    if (idx < (F_IN / 2) * F_HID) {
        int k2 = idx >> 8;
        int nn = idx & 255;
        g_w1p[idx] = packh2(W1[(2 * k2) * F_HID + nn], W1[(2 * k2 + 1) * F_HID + nn]);
    }
}

// ---------------- fp16 tensor-core GEMM1 (mma.sync.m16n8k16) ----------------
__device__ __forceinline__ void mma16(float c[4], const unsigned a[4], const unsigned b[2]) {
    asm volatile(
        "mma.sync.aligned.m16n8k16.row.col.f32.f16.f16.f32 "
        "{%0,%1,%2,%3}, {%4,%5,%6,%7}, {%8,%9}, {%0,%1,%2,%3};"
        : "+f"(c[0]), "+f"(c[1]), "+f"(c[2]), "+f"(c[3])
        : "r"(a[0]), "r"(a[1]), "r"(a[2]), "r"(a[3]), "r"(b[0]), "r"(b[1]));
}

#define SPAD 136

__global__ __launch_bounds__(256, 2) void k_gemm1_h(const float* __restrict__ A, int M) {
    __shared__ unsigned As2[2][16][SPAD];
    __shared__ unsigned Bs2[2][16][SPAD];

    const int tid  = threadIdx.x;
    const int lane = tid & 31;
    const int wid  = tid >> 5;
    const int wm   = wid & 1;
    const int wn   = wid >> 1;
    const int bx   = blockIdx.x;
    const long mBase = (long)blockIdx.y * 128;

    const int  rowA = tid & 127;
    const int  kfA  = (tid >> 7) * 16;
    const int  k2A  = kfA >> 1;
    const long gRowA = mBase + rowA;
    const bool okA   = gRowA < M;
    const float* Ag  = A + gRowA * F_IN + kfA;

    const int krB  = tid >> 4;
    const int colB = (tid & 15) * 8;
    const unsigned* Wp = g_w1p + (long)bx * 128 + colB;

    float fa[16];
    uint4 ub0, ub1;

    if (okA) {
#pragma unroll
        for (int j = 0; j < 4; j++) *(float4*)&fa[j * 4] = *(const float4*)(Ag + j * 4);
    } else {
#pragma unroll
        for (int j = 0; j < 16; j++) fa[j] = 0.f;
    }
    ub0 = *(const uint4*)(Wp + (long)krB * F_HID);
    ub1 = *(const uint4*)(Wp + (long)krB * F_HID + 4);

#pragma unroll
    for (int j = 0; j < 8; j++) As2[0][k2A + j][rowA] = packh2(fa[2 * j], fa[2 * j + 1]);
    *(uint4*)&Bs2[0][krB][colB]     = ub0;
    *(uint4*)&Bs2[0][krB][colB + 4] = ub1;
    __syncthreads();

    float c[4][4][4];
#pragma unroll
    for (int mt = 0; mt < 4; mt++)
#pragma unroll
        for (int nt = 0; nt < 4; nt++)
#pragma unroll
            for (int q = 0; q < 4; q++) c[mt][nt][q] = 0.f;

    int cur = 0;
    const int NITER = F_IN / 32;
    for (int it = 0; it < NITER; ++it) {
        if (it + 1 < NITER) {
            int kf = (it + 1) * 32;
            if (okA) {
#pragma unroll
                for (int j = 0; j < 4; j++) *(float4*)&fa[j * 4] = *(const float4*)(Ag + kf + j * 4);
            }
            ub0 = *(const uint4*)(Wp + (long)(kf / 2 + krB) * F_HID);
            ub1 = *(const uint4*)(Wp + (long)(kf / 2 + krB) * F_HID + 4);
        }

#pragma unroll
        for (int kk = 0; kk < 16; kk += 8) {
            const int k2q = kk + (lane & 3);
            const int p   = lane >> 2;
            unsigned afr[4][4], bfr[4][2];
#pragma unroll
            for (int mt = 0; mt < 4; mt++) {
                int r = wm * 64 + mt * 16 + p;
                afr[mt][0] = As2[cur][k2q][r];
                afr[mt][1] = As2[cur][k2q][r + 8];
                afr[mt][2] = As2[cur][k2q + 4][r];
                afr[mt][3] = As2[cur][k2q + 4][r + 8];
            }
#pragma unroll
            for (int nt = 0; nt < 4; nt++) {
                int cc = wn * 32 + nt * 8 + p;
                bfr[nt][0] = Bs2[cur][k2q][cc];
                bfr[nt][1] = Bs2[cur][k2q + 4][cc];
            }
#pragma unroll
            for (int mt = 0; mt < 4; mt++)
#pragma unroll
                for (int nt = 0; nt < 4; nt++)
                    mma16(c[mt][nt], afr[mt], bfr[nt]);
        }

        if (it + 1 < NITER) {
            int nxt = cur ^ 1;
#pragma unroll
            for (int j = 0; j < 8; j++) As2[nxt][k2A + j][rowA] = packh2(fa[2 * j], fa[2 * j + 1]);
            *(uint4*)&Bs2[nxt][krB][colB]     = ub0;
            *(uint4*)&Bs2[nxt][krB][colB + 4] = ub1;
            __syncthreads();
            cur = nxt;
        }
    }

    const int p  = lane >> 2;
    const int q2 = (lane & 3) * 2;
#pragma unroll
    for (int mt = 0; mt < 4; mt++) {
        long r0 = mBase + wm * 64 + mt * 16 + p;
        long r1 = r0 + 8;
        if (r0 < M) {
            float dv = g_dinv[r0];
#pragma unroll
            for (int nt = 0; nt < 4; nt++) {
                int col = bx * 128 + wn * 32 + nt * 8 + q2;
                g_hh[r0 * (F_HID/2) + (col >> 1)] = packh2(c[mt][nt][0] * dv, c[mt][nt][1] * dv);
            }
        }
        if (r1 < M) {
            float dv = g_dinv[r1];
#pragma unroll
            for (int nt = 0; nt < 4; nt++) {
                int col = bx * 128 + wn * 32 + nt * 8 + q2;
                g_hh[r1 * (F_HID/2) + (col >> 1)] = packh2(c[mt][nt][2] * dv, c[mt][nt][3] * dv);
            }
        }
    }
}

// ---------------- agg1 + bias + relu + GEMM2 fused (fp16 h gather, fp16 h2 out) ----------------
__global__ __launch_bounds__(256) void k_agg1(const float* __restrict__ b1, int n) {
    __shared__ float w2s[F_OUT * F_HID];   // 40 KB
    __shared__ float hsm[F_HID];
    __shared__ float pA[128], pB[128];
    __shared__ float h2f[F_OUT];
    __shared__ int   jsm[256];
    int tid = threadIdx.x;
    for (int idx = tid; idx < F_OUT * F_HID; idx += 256) w2s[idx] = g_w2t[idx];
    __syncthreads();

    const int half = tid >> 7;
    const int f2   = tid & 127;
    const int lane = tid & 31, w = tid >> 5;
    const float bias0 = b1[2 * f2];
    const float bias1 = b1[2 * f2 + 1];

    for (int i = blockIdx.x; i < n; i += gridDim.x) {
        int start = g_rowptr[i];
        int end   = g_rowptr[i + 1];

        float acc0 = 0.f, acc1 = 0.f;
        if (half == 0) {   // self-loop (already dinv-scaled)
            unsigned u = g_hh[(long)i * 128 + f2];
            __half2 hh = *(__half2*)&u;
            acc0 = __low2float(hh);
            acc1 = __high2float(hh);
        }

        for (int base = start; base < end; base += 256) {
            int m = min(256, end - base);
            __syncthreads();
            if (tid < m) jsm[tid] = g_adj[base + tid];
            __syncthreads();
            int t = half;
            float d0 = 0.f, d1 = 0.f;   // second independent chain
            for (; t + 2 < m; t += 4) {
                long ja = jsm[t], jb = jsm[t + 2];
                unsigned ua = g_hh[ja * 128 + f2];
                unsigned ub = g_hh[jb * 128 + f2];
                __half2 ha = *(__half2*)&ua;
                __half2 hb = *(__half2*)&ub;
                acc0 += __low2float(ha);  acc1 += __high2float(ha);
                d0   += __low2float(hb);  d1   += __high2float(hb);
            }
            for (; t < m; t += 2) {
                long j = jsm[t];
                unsigned u = g_hh[j * 128 + f2];
                __half2 hh = *(__half2*)&u;
                acc0 += __low2float(hh);
                acc1 += __high2float(hh);
            }
            acc0 += d0; acc1 += d1;
        }

        if (half == 1) { pA[f2] = acc0; pB[f2] = acc1; }
        __syncthreads();
        if (half == 0) {
            float dv = g_dinv[i];
            hsm[2 * f2]     = fmaxf(fmaf(acc0 + pA[f2], dv, bias0), 0.f);
            hsm[2 * f2 + 1] = fmaxf(fmaf(acc1 + pB[f2], dv, bias1), 0.f);
        }
        __syncthreads();

        // GEMM2: 8 warps x 5 outputs
        float hv[8];
#pragma unroll
        for (int k = 0; k < 8; k++) hv[k] = hsm[(k << 5) + lane];
        float dvi = g_dinv[i];
#pragma unroll
        for (int oo = 0; oo < 5; oo++) {
            int o = w * 5 + oo;
            const float* wrow = &w2s[o * F_HID];
            float p = 0.f;
#pragma unroll
            for (int k = 0; k < 8; k++) p = fmaf(hv[k], wrow[(k << 5) + lane], p);
#pragma unroll
            for (int off = 16; off; off >>= 1)
                p += __shfl_xor_sync(0xffffffffu, p, off);
            if (lane == 0) h2f[o] = p * dvi;
        }
        __syncthreads();
        if (tid < F_OUT / 2)
            g_h2h[(long)i * (F_OUT / 2) + tid] = packh2(h2f[2 * tid], h2f[2 * tid + 1]);
    }
}

// ---------------- agg2 + bias + log_softmax (fp16 h2 gather) ----------------
// warp per node; lane l < 20 owns feature pair (2l, 2l+1).
__global__ __launch_bounds__(256) void k_agg2(const float* __restrict__ b2,
                                              float* __restrict__ outF,
                                              float* __restrict__ outL,
                                              int n, int writeL) {
    int lane = threadIdx.x & 31;
    int wid  = (blockIdx.x * blockDim.x + threadIdx.x) >> 5;
    int nw   = (gridDim.x * blockDim.x) >> 5;
    bool act = lane < (F_OUT / 2);
    float bias0 = act ? b2[2 * lane] : 0.f;
    float bias1 = act ? b2[2 * lane + 1] : 0.f;

    for (int i = wid; i < n; i += nw) {
        int start = g_rowptr[i];
        int end   = g_rowptr[i + 1];
        float a0 = 0.f, a1 = 0.f;
        if (act) {
            unsigned u = g_h2h[(long)i * 20 + lane];
            __half2 hh = *(__half2*)&u;
            a0 = __low2float(hh);
            a1 = __high2float(hh);
        }
#pragma unroll 4
        for (int e = start; e < end; e++) {
            int j = g_adj[e];
            if (act) {
                unsigned u = g_h2h[(long)j * 20 + lane];
                __half2 hh = *(__half2*)&u;
                a0 += __low2float(hh);
                a1 += __high2float(hh);
            }
        }
        float dv = g_dinv[i];
        long ib = (long)i * F_OUT;
        float f0 = fmaf(a0, dv, bias0);
        float f1 = fmaf(a1, dv, bias1);
        if (act) *(float2*)(outF + ib + 2 * lane) = make_float2(f0, f1);

        if (writeL) {
            float mx = act ? fmaxf(f0, f1) : -INFINITY;
#pragma unroll
            for (int off = 16; off; off >>= 1)
                mx = fmaxf(mx, __shfl_xor_sync(0xffffffffu, mx, off));
            float s = act ? (expf(f0 - mx) + expf(f1 - mx)) : 0.f;
#pragma unroll
            for (int off = 16; off; off >>= 1)
                s += __shfl_xor_sync(0xffffffffu, s, off);
            float lse = mx + logf(s);
            if (act) *(float2*)(outL + ib + 2 * lane) = make_float2(f0 - lse, f1 - lse);
        }
    }
}

// ---------------- launch ----------------
extern "C" void kernel_launch(void* const* d_in, const int* in_sizes, int n_in,
                              void* d_out, int out_size) {
    const float* x  = (const float*)d_in[0];
    const void*  ei = d_in[1];
    const float* W1 = (const float*)d_in[2];
    const float* b1 = (const float*)d_in[3];
    const float* W2 = (const float*)d_in[4];
    const float* b2 = (const float*)d_in[5];

    int n = in_sizes[0] / F_IN;
    int E = in_sizes[1] / 2;

    float* out = (float*)d_out;
    int half = n * F_OUT;
    float* outF = out;
    float* outL = out;
    int writeL = 0;
    if (out_size >= 2 * half) { outL = out + half; writeL = 1; }

    int nb = (n + 1023) >> 10;

    k_init   <<<(n + 255) / 256, 256>>>(n);
    k_detect <<<64, 256>>>((const long long*)ei, E, n);
    k_hist   <<<2048, 256>>>(ei, E, n);
    k_dinv   <<<(n + 255) / 256, 256>>>(n);
    k_scan1  <<<nb, 1024>>>(n);
    k_scan2  <<<1, 256>>>(nb);
    k_scan3  <<<(n + 255) / 256, 256>>>(n, E);
    k_fill   <<<2048, 256>>>(ei, E, n);
    k_tw2    <<<(F_OUT * F_HID + 255) / 256, 256>>>(W2);
    k_tw1p   <<<((F_IN / 2) * F_HID + 255) / 256, 256>>>(W1);

    dim3 g1(2, (n + 127) / 128);
    k_gemm1_h<<<g1, 256>>>(x, n);

    k_agg1<<<4096, 256>>>(b1, n);
    k_agg2<<<2048, 256>>>(b2, outF, outL, n, writeL);
}

// round 11
// speedup vs baseline: 1.0200x; 1.0200x over previous
#include <cuda_runtime.h>
#include <cuda_bf16.h>
#include <cuda_fp16.h>
#include <stdint.h>
#include <math.h>

// Problem constants (fixed by the reference)
#define F_IN   512
#define F_HID  256
#define F_OUT  40
#define MAXN   100000
#define MAXE   3200000

// ---------------- scratch (device globals; no runtime allocation) ----------------
__device__ int   g_is32;
__device__ int   g_eidx[2 * MAXE];
__device__ int   g_deg[MAXN];
__device__ int   g_cnt[MAXN];
__device__ float g_dinv[MAXN];
__device__ int   g_rowptr[MAXN + 1];
__device__ int   g_cursor[MAXN];
__device__ int   g_adj[MAXE];
__device__ int   g_part[256];
__device__ float g_w2t[F_OUT * F_HID];
__device__ unsigned g_w1p[(F_IN / 2) * F_HID];    // W1 packed half2 along k: [k2][n]
__device__ unsigned g_hh[(long)MAXN * (F_HID/2)]; // h_s half2-packed (dinv*x@W1)
__device__ unsigned g_h2h[(long)MAXN * (F_OUT/2)];// h2_s half2-packed (dinv*relu@W2)

// ---------------- helpers ----------------
__device__ __forceinline__ unsigned packh2(float lo, float hi) {
    __half2 h = __floats2half2_rn(lo, hi);
    return *(unsigned*)&h;
}

// ---------------- fused prep: init counters + transpose W2 + pack W1 ----------------
// blocks [0, nbI)           : init g_deg/g_cnt
// blocks [nbI, nbI+40)      : tw2 (40*256 elems)
// blocks [nbI+40, nbI+296)  : tw1p (256*256 elems)
__global__ void k_prep(int n, int nbI, const float* __restrict__ W2,
                       const float* __restrict__ W1) {
    int b = blockIdx.x;
    int t = threadIdx.x;
    if (b < nbI) {
        int i = b * 256 + t;
        if (i < n) { g_deg[i] = 1; g_cnt[i] = 0; }
        if (b == 0 && t == 0) g_is32 = 0;
    } else if (b < nbI + 40) {
        int idx = (b - nbI) * 256 + t;          // < F_OUT*F_HID
        int o = idx / F_HID, f = idx % F_HID;
        g_w2t[idx] = W2[f * F_OUT + o];
    } else {
        int idx = (b - nbI - 40) * 256 + t;     // < 256*256
        int k2 = idx >> 8;
        int nn = idx & 255;
        g_w1p[idx] = packh2(W1[(2 * k2) * F_HID + nn], W1[(2 * k2 + 1) * F_HID + nn]);
    }
}

// Sample first 64K int64 words: any out-of-range value => data is really int32.
__global__ void k_detect(const long long* __restrict__ ei, int E, int n) {
    int cnt = min(E, 1 << 16);
    int bad = 0;
    for (int e = blockIdx.x * blockDim.x + threadIdx.x; e < cnt; e += gridDim.x * blockDim.x) {
        long long v = ei[e];
        if (v < 0 || v >= n) bad = 1;
    }
    if (__syncthreads_or(bad)) {
        if (threadIdx.x == 0) g_is32 = 1;
    }
}

// convert raw -> int32 g_eidx, with fused degree histogram
__global__ void k_convert(const void* __restrict__ ei_raw, int E, int n) {
    int is32 = g_is32;
    const int*       e32 = (const int*)ei_raw;
    const long long* e64 = (const long long*)ei_raw;
    for (long e = blockIdx.x * blockDim.x + threadIdx.x; e < 2L * E; e += (long)gridDim.x * blockDim.x) {
        long long v = is32 ? (long long)e32[e] : e64[e];
        if (v < 0) v = 0;
        if (v >= n) v = n - 1;
        int vi = (int)v;
        g_eidx[e] = vi;
        if (e < E) atomicAdd(&g_cnt[vi], 1);   // row counts
        else       atomicAdd(&g_deg[vi], 1);   // col degrees
    }
}

__global__ void k_dinv(int n) {
    int i = blockIdx.x * blockDim.x + threadIdx.x;
    if (i < n) g_dinv[i] = rsqrtf((float)g_deg[i]);
}

// ---------------- CSR build ----------------
__global__ void k_scan1(int n) {
    __shared__ int s[1024];
    int tid = threadIdx.x;
    int idx = blockIdx.x * 1024 + tid;
    int v = (idx < n) ? g_cnt[idx] : 0;
    s[tid] = v;
    __syncthreads();
    for (int off = 1; off < 1024; off <<= 1) {
        int t = (tid >= off) ? s[tid - off] : 0;
        __syncthreads();
        s[tid] += t;
        __syncthreads();
    }
    if (idx < n) g_rowptr[idx] = s[tid] - v;
    if (tid == 1023) g_part[blockIdx.x] = s[1023];
}

__global__ void k_scan2(int nb) {
    __shared__ int s[256];
    int tid = threadIdx.x;
    int v = (tid < nb) ? g_part[tid] : 0;
    s[tid] = v;
    __syncthreads();
    for (int off = 1; off < 256; off <<= 1) {
        int t = (tid >= off) ? s[tid - off] : 0;
        __syncthreads();
        s[tid] += t;
        __syncthreads();
    }
    if (tid < nb) g_part[tid] = s[tid] - v;
}

__global__ void k_scan3(int n, int E) {
    int i = blockIdx.x * blockDim.x + threadIdx.x;
    if (i < n) {
        int rp = g_rowptr[i] + g_part[i >> 10];
        g_rowptr[i] = rp;
        g_cursor[i] = rp;
    }
    if (blockIdx.x == 0 && threadIdx.x == 0) g_rowptr[n] = E;
}

__global__ void k_fill(int E) {
    for (int e = blockIdx.x * blockDim.x + threadIdx.x; e < E; e += gridDim.x * blockDim.x) {
        int r = g_eidx[e];
        int c = g_eidx[E + e];
        int pos = atomicAdd(&g_cursor[r], 1);
        g_adj[pos] = c;
    }
}

// ---------------- fp16 tensor-core GEMM1 (mma.sync.m16n8k16) ----------------
__device__ __forceinline__ void mma16(float c[4], const unsigned a[4], const unsigned b[2]) {
    asm volatile(
        "mma.sync.aligned.m16n8k16.row.col.f32.f16.f16.f32 "
        "{%0,%1,%2,%3}, {%4,%5,%6,%7}, {%8,%9}, {%0,%1,%2,%3};"
        : "+f"(c[0]), "+f"(c[1]), "+f"(c[2]), "+f"(c[3])
        : "r"(a[0]), "r"(a[1]), "r"(a[2]), "r"(a[3]), "r"(b[0]), "r"(b[1]));
}

#define SPAD 136

__global__ __launch_bounds__(256, 2) void k_gemm1_h(const float* __restrict__ A, int M) {
    __shared__ unsigned As2[2][16][SPAD];
    __shared__ unsigned Bs2[2][16][SPAD];

    const int tid  = threadIdx.x;
    const int lane = tid & 31;
    const int wid  = tid >> 5;
    const int wm   = wid & 1;
    const int wn   = wid >> 1;
    const int bx   = blockIdx.x;
    const long mBase = (long)blockIdx.y * 128;

    const int  rowA = tid & 127;
    const int  kfA  = (tid >> 7) * 16;
    const int  k2A  = kfA >> 1;
    const long gRowA = mBase + rowA;
    const bool okA   = gRowA < M;
    const float* Ag  = A + gRowA * F_IN + kfA;

    const int krB  = tid >> 4;
    const int colB = (tid & 15) * 8;
    const unsigned* Wp = g_w1p + (long)bx * 128 + colB;

    float fa[16];
    uint4 ub0, ub1;

    if (okA) {
#pragma unroll
        for (int j = 0; j < 4; j++) *(float4*)&fa[j * 4] = *(const float4*)(Ag + j * 4);
    } else {
#pragma unroll
        for (int j = 0; j < 16; j++) fa[j] = 0.f;
    }
    ub0 = *(const uint4*)(Wp + (long)krB * F_HID);
    ub1 = *(const uint4*)(Wp + (long)krB * F_HID + 4);

#pragma unroll
    for (int j = 0; j < 8; j++) As2[0][k2A + j][rowA] = packh2(fa[2 * j], fa[2 * j + 1]);
    *(uint4*)&Bs2[0][krB][colB]     = ub0;
    *(uint4*)&Bs2[0][krB][colB + 4] = ub1;
    __syncthreads();

    float c[4][4][4];
#pragma unroll
    for (int mt = 0; mt < 4; mt++)
#pragma unroll
        for (int nt = 0; nt < 4; nt++)
#pragma unroll
            for (int q = 0; q < 4; q++) c[mt][nt][q] = 0.f;

    int cur = 0;
    const int NITER = F_IN / 32;
    for (int it = 0; it < NITER; ++it) {
        if (it + 1 < NITER) {
            int kf = (it + 1) * 32;
            if (okA) {
#pragma unroll
                for (int j = 0; j < 4; j++) *(float4*)&fa[j * 4] = *(const float4*)(Ag + kf + j * 4);
            }
            ub0 = *(const uint4*)(Wp + (long)(kf / 2 + krB) * F_HID);
            ub1 = *(const uint4*)(Wp + (long)(kf / 2 + krB) * F_HID + 4);
        }

#pragma unroll
        for (int kk = 0; kk < 16; kk += 8) {
            const int k2q = kk + (lane & 3);
            const int p   = lane >> 2;
            unsigned afr[4][4], bfr[4][2];
#pragma unroll
            for (int mt = 0; mt < 4; mt++) {
                int r = wm * 64 + mt * 16 + p;
                afr[mt][0] = As2[cur][k2q][r];
                afr[mt][1] = As2[cur][k2q][r + 8];
                afr[mt][2] = As2[cur][k2q + 4][r];
                afr[mt][3] = As2[cur][k2q + 4][r + 8];
            }
#pragma unroll
            for (int nt = 0; nt < 4; nt++) {
                int cc = wn * 32 + nt * 8 + p;
                bfr[nt][0] = Bs2[cur][k2q][cc];
                bfr[nt][1] = Bs2[cur][k2q + 4][cc];
            }
#pragma unroll
            for (int mt = 0; mt < 4; mt++)
#pragma unroll
                for (int nt = 0; nt < 4; nt++)
                    mma16(c[mt][nt], afr[mt], bfr[nt]);
        }

        if (it + 1 < NITER) {
            int nxt = cur ^ 1;
#pragma unroll
            for (int j = 0; j < 8; j++) As2[nxt][k2A + j][rowA] = packh2(fa[2 * j], fa[2 * j + 1]);
            *(uint4*)&Bs2[nxt][krB][colB]     = ub0;
            *(uint4*)&Bs2[nxt][krB][colB + 4] = ub1;
            __syncthreads();
            cur = nxt;
        }
    }

    const int p  = lane >> 2;
    const int q2 = (lane & 3) * 2;
#pragma unroll
    for (int mt = 0; mt < 4; mt++) {
        long r0 = mBase + wm * 64 + mt * 16 + p;
        long r1 = r0 + 8;
        if (r0 < M) {
            float dv = g_dinv[r0];
#pragma unroll
            for (int nt = 0; nt < 4; nt++) {
                int col = bx * 128 + wn * 32 + nt * 8 + q2;
                g_hh[r0 * (F_HID/2) + (col >> 1)] = packh2(c[mt][nt][0] * dv, c[mt][nt][1] * dv);
            }
        }
        if (r1 < M) {
            float dv = g_dinv[r1];
#pragma unroll
            for (int nt = 0; nt < 4; nt++) {
                int col = bx * 128 + wn * 32 + nt * 8 + q2;
                g_hh[r1 * (F_HID/2) + (col >> 1)] = packh2(c[mt][nt][2] * dv, c[mt][nt][3] * dv);
            }
        }
    }
}

// ---------------- agg1 + bias + relu + GEMM2 fused (fp16 h gather, fp16 h2 out) ----------------
// Block = 256 threads = 2 halves x 128. Each half processes alternate edges;
// lane f2 of a half owns feature pair (2*f2, 2*f2+1). fp32 accumulate.
__global__ __launch_bounds__(256) void k_agg1(const float* __restrict__ b1, int n) {
    __shared__ float w2s[F_OUT * F_HID];   // 40 KB
    __shared__ float hsm[F_HID];
    __shared__ float pA[128], pB[128];
    __shared__ float h2f[F_OUT];
    __shared__ int   jsm[256];
    int tid = threadIdx.x;
    for (int idx = tid; idx < F_OUT * F_HID; idx += 256) w2s[idx] = g_w2t[idx];
    __syncthreads();

    const int half = tid >> 7;
    const int f2   = tid & 127;
    const int lane = tid & 31, w = tid >> 5;
    const float bias0 = b1[2 * f2];
    const float bias1 = b1[2 * f2 + 1];

    for (int i = blockIdx.x; i < n; i += gridDim.x) {
        int start = g_rowptr[i];
        int end   = g_rowptr[i + 1];

        float acc0 = 0.f, acc1 = 0.f;
        if (half == 0) {   // self-loop (already dinv-scaled)
            unsigned u = g_hh[(long)i * 128 + f2];
            __half2 hh = *(__half2*)&u;
            acc0 = __low2float(hh);
            acc1 = __high2float(hh);
        }

        for (int base = start; base < end; base += 256) {
            int m = min(256, end - base);
            __syncthreads();
            if (tid < m) jsm[tid] = g_adj[base + tid];
            __syncthreads();
            for (int t = half; t < m; t += 2) {
                long j = jsm[t];
                unsigned u = g_hh[j * 128 + f2];
                __half2 hh = *(__half2*)&u;
                acc0 += __low2float(hh);
                acc1 += __high2float(hh);
            }
        }

        if (half == 1) { pA[f2] = acc0; pB[f2] = acc1; }
        __syncthreads();
        if (half == 0) {
            float dv = g_dinv[i];
            hsm[2 * f2]     = fmaxf(fmaf(acc0 + pA[f2], dv, bias0), 0.f);
            hsm[2 * f2 + 1] = fmaxf(fmaf(acc1 + pB[f2], dv, bias1), 0.f);
        }
        __syncthreads();

        // GEMM2: 8 warps x 5 outputs; lane l owns f = l, l+32, ..., l+224
        float hv[8];
#pragma unroll
        for (int k = 0; k < 8; k++) hv[k] = hsm[(k << 5) + lane];
        float dvi = g_dinv[i];
#pragma unroll
        for (int oo = 0; oo < 5; oo++) {
            int o = w * 5 + oo;
            const float* wrow = &w2s[o * F_HID];
            float p = 0.f;
#pragma unroll
            for (int k = 0; k < 8; k++) p = fmaf(hv[k], wrow[(k << 5) + lane], p);
#pragma unroll
            for (int off = 16; off; off >>= 1)
                p += __shfl_xor_sync(0xffffffffu, p, off);
            if (lane == 0) h2f[o] = p * dvi;
        }
        __syncthreads();
        if (tid < F_OUT / 2)
            g_h2h[(long)i * (F_OUT / 2) + tid] = packh2(h2f[2 * tid], h2f[2 * tid + 1]);
    }
}

// ---------------- agg2 + bias + log_softmax (fp16 h2 gather) ----------------
// warp per node; lane l < 20 owns feature pair (2l, 2l+1).
__global__ __launch_bounds__(256) void k_agg2(const float* __restrict__ b2,
                                              float* __restrict__ outF,
                                              float* __restrict__ outL,
                                              int n, int writeL) {
    int lane = threadIdx.x & 31;
    int wid  = (blockIdx.x * blockDim.x + threadIdx.x) >> 5;
    int nw   = (gridDim.x * blockDim.x) >> 5;
    bool act = lane < (F_OUT / 2);
    float bias0 = act ? b2[2 * lane] : 0.f;
    float bias1 = act ? b2[2 * lane + 1] : 0.f;

    for (int i = wid; i < n; i += nw) {
        int start = g_rowptr[i];
        int end   = g_rowptr[i + 1];
        float a0 = 0.f, a1 = 0.f;
        if (act) {
            unsigned u = g_h2h[(long)i * 20 + lane];
            __half2 hh = *(__half2*)&u;
            a0 = __low2float(hh);
            a1 = __high2float(hh);
        }
#pragma unroll 4
        for (int e = start; e < end; e++) {
            int j = g_adj[e];
            if (act) {
                unsigned u = g_h2h[(long)j * 20 + lane];
                __half2 hh = *(__half2*)&u;
                a0 += __low2float(hh);
                a1 += __high2float(hh);
            }
        }
        float dv = g_dinv[i];
        long ib = (long)i * F_OUT;
        float f0 = fmaf(a0, dv, bias0);
        float f1 = fmaf(a1, dv, bias1);
        if (act) *(float2*)(outF + ib + 2 * lane) = make_float2(f0, f1);

        if (writeL) {
            float mx = act ? fmaxf(f0, f1) : -INFINITY;
#pragma unroll
            for (int off = 16; off; off >>= 1)
                mx = fmaxf(mx, __shfl_xor_sync(0xffffffffu, mx, off));
            float s = act ? (expf(f0 - mx) + expf(f1 - mx)) : 0.f;
#pragma unroll
            for (int off = 16; off; off >>= 1)
                s += __shfl_xor_sync(0xffffffffu, s, off);
            float lse = mx + logf(s);
            if (act) *(float2*)(outL + ib + 2 * lane) = make_float2(f0 - lse, f1 - lse);
        }
    }
}

// ---------------- launch ----------------
extern "C" void kernel_launch(void* const* d_in, const int* in_sizes, int n_in,
                              void* d_out, int out_size) {
    const float* x  = (const float*)d_in[0];
    const void*  ei = d_in[1];
    const float* W1 = (const float*)d_in[2];
    const float* b1 = (const float*)d_in[3];
    const float* W2 = (const float*)d_in[4];
    const float* b2 = (const float*)d_in[5];

    int n = in_sizes[0] / F_IN;
    int E = in_sizes[1] / 2;

    float* out = (float*)d_out;
    int half = n * F_OUT;
    float* outF = out;
    float* outL = out;
    int writeL = 0;
    if (out_size >= 2 * half) { outL = out + half; writeL = 1; }

    int nb  = (n + 1023) >> 10;
    int nbI = (n + 255) / 256;

    k_prep   <<<nbI + 40 + 256, 256>>>(n, nbI, W2, W1);
    k_detect <<<64, 256>>>((const long long*)ei, E, n);
    k_convert<<<2048, 256>>>(ei, E, n);
    k_dinv   <<<nbI, 256>>>(n);
    k_scan1  <<<nb, 1024>>>(n);
    k_scan2  <<<1, 256>>>(nb);
    k_scan3  <<<nbI, 256>>>(n, E);
    k_fill   <<<2048, 256>>>(E);

    dim3 g1(2, (n + 127) / 128);
    k_gemm1_h<<<g1, 256>>>(x, n);

    k_agg1<<<4096, 256>>>(b1, n);
    k_agg2<<<2048, 256>>>(b2, outF, outL, n, writeL);
}

// round 12
// speedup vs baseline: 1.0389x; 1.0185x over previous
#include <cuda_runtime.h>
#include <cuda_bf16.h>
#include <cuda_fp16.h>
#include <stdint.h>
#include <math.h>

// Problem constants (fixed by the reference)
#define F_IN   512
#define F_HID  256
#define F_OUT  40
#define MAXN   100000
#define MAXE   3200000

// ---------------- scratch (device globals; no runtime allocation) ----------------
__device__ int   g_is32;
__device__ int   g_eidx[2 * MAXE];
__device__ int   g_deg[MAXN];
__device__ int   g_cnt[MAXN];
__device__ float g_dinv[MAXN];
__device__ int   g_rowptr[MAXN + 1];
__device__ int   g_cursor[MAXN];
__device__ int   g_adj[MAXE];
__device__ int   g_part[256];
__device__ float g_w2t[F_OUT * F_HID];
__device__ unsigned g_w1p[(F_IN / 2) * F_HID];    // W1 packed half2 along k: [k2][n]
__device__ unsigned g_hh[(long)MAXN * (F_HID/2)]; // h half2-packed (x@W1, UNSCALED)
__device__ float g_h2[(long)MAXN * F_OUT];        // h2_s = dinv[i] * (relu(...) @ W2)

// ---------------- helpers ----------------
__device__ __forceinline__ unsigned packh2(float lo, float hi) {
    __half2 h = __floats2half2_rn(lo, hi);
    return *(unsigned*)&h;
}

// ---------------- prep A (edge-chain stream): init counters + transpose W2 ----------------
__global__ void k_prepA(int n, int nbI, const float* __restrict__ W2) {
    int b = blockIdx.x;
    int t = threadIdx.x;
    if (b < nbI) {
        int i = b * 256 + t;
        if (i < n) { g_deg[i] = 1; g_cnt[i] = 0; }
        if (b == 0 && t == 0) g_is32 = 0;
    } else {
        int idx = (b - nbI) * 256 + t;          // < F_OUT*F_HID
        int o = idx / F_HID, f = idx % F_HID;
        g_w2t[idx] = W2[f * F_OUT + o];
    }
}

// ---------------- prep B (gemm stream): pack W1 ----------------
__global__ void k_w1p(const float* __restrict__ W1) {
    int idx = blockIdx.x * blockDim.x + threadIdx.x;   // < 256*256
    int k2 = idx >> 8;
    int nn = idx & 255;
    g_w1p[idx] = packh2(W1[(2 * k2) * F_HID + nn], W1[(2 * k2 + 1) * F_HID + nn]);
}

// Sample first 64K int64 words: any out-of-range value => data is really int32.
__global__ void k_detect(const long long* __restrict__ ei, int E, int n) {
    int cnt = min(E, 1 << 16);
    int bad = 0;
    for (int e = blockIdx.x * blockDim.x + threadIdx.x; e < cnt; e += gridDim.x * blockDim.x) {
        long long v = ei[e];
        if (v < 0 || v >= n) bad = 1;
    }
    if (__syncthreads_or(bad)) {
        if (threadIdx.x == 0) g_is32 = 1;
    }
}

// convert raw -> int32 g_eidx, with fused degree histogram
__global__ void k_convert(const void* __restrict__ ei_raw, int E, int n) {
    int is32 = g_is32;
    const int*       e32 = (const int*)ei_raw;
    const long long* e64 = (const long long*)ei_raw;
    for (long e = blockIdx.x * blockDim.x + threadIdx.x; e < 2L * E; e += (long)gridDim.x * blockDim.x) {
        long long v = is32 ? (long long)e32[e] : e64[e];
        if (v < 0) v = 0;
        if (v >= n) v = n - 1;
        int vi = (int)v;
        g_eidx[e] = vi;
        if (e < E) atomicAdd(&g_cnt[vi], 1);   // row counts
        else       atomicAdd(&g_deg[vi], 1);   // col degrees
    }
}

__global__ void k_dinv(int n) {
    int i = blockIdx.x * blockDim.x + threadIdx.x;
    if (i < n) g_dinv[i] = rsqrtf((float)g_deg[i]);
}

// ---------------- CSR build ----------------
__global__ void k_scan1(int n) {
    __shared__ int s[1024];
    int tid = threadIdx.x;
    int idx = blockIdx.x * 1024 + tid;
    int v = (idx < n) ? g_cnt[idx] : 0;
    s[tid] = v;
    __syncthreads();
    for (int off = 1; off < 1024; off <<= 1) {
        int t = (tid >= off) ? s[tid - off] : 0;
        __syncthreads();
        s[tid] += t;
        __syncthreads();
    }
    if (idx < n) g_rowptr[idx] = s[tid] - v;
    if (tid == 1023) g_part[blockIdx.x] = s[1023];
}

__global__ void k_scan2(int nb) {
    __shared__ int s[256];
    int tid = threadIdx.x;
    int v = (tid < nb) ? g_part[tid] : 0;
    s[tid] = v;
    __syncthreads();
    for (int off = 1; off < 256; off <<= 1) {
        int t = (tid >= off) ? s[tid - off] : 0;
        __syncthreads();
        s[tid] += t;
        __syncthreads();
    }
    if (tid < nb) g_part[tid] = s[tid] - v;
}

__global__ void k_scan3(int n, int E) {
    int i = blockIdx.x * blockDim.x + threadIdx.x;
    if (i < n) {
        int rp = g_rowptr[i] + g_part[i >> 10];
        g_rowptr[i] = rp;
        g_cursor[i] = rp;
    }
    if (blockIdx.x == 0 && threadIdx.x == 0) g_rowptr[n] = E;
}

__global__ void k_fill(int E) {
    for (int e = blockIdx.x * blockDim.x + threadIdx.x; e < E; e += gridDim.x * blockDim.x) {
        int r = g_eidx[e];
        int c = g_eidx[E + e];
        int pos = atomicAdd(&g_cursor[r], 1);
        g_adj[pos] = c;
    }
}

// ---------------- fp16 tensor-core GEMM1 (mma.sync.m16n8k16), NO dinv scaling ----------------
__device__ __forceinline__ void mma16(float c[4], const unsigned a[4], const unsigned b[2]) {
    asm volatile(
        "mma.sync.aligned.m16n8k16.row.col.f32.f16.f16.f32 "
        "{%0,%1,%2,%3}, {%4,%5,%6,%7}, {%8,%9}, {%0,%1,%2,%3};"
        : "+f"(c[0]), "+f"(c[1]), "+f"(c[2]), "+f"(c[3])
        : "r"(a[0]), "r"(a[1]), "r"(a[2]), "r"(a[3]), "r"(b[0]), "r"(b[1]));
}

#define SPAD 136

__global__ __launch_bounds__(256, 2) void k_gemm1_h(const float* __restrict__ A, int M) {
    __shared__ unsigned As2[2][16][SPAD];
    __shared__ unsigned Bs2[2][16][SPAD];

    const int tid  = threadIdx.x;
    const int lane = tid & 31;
    const int wid  = tid >> 5;
    const int wm   = wid & 1;
    const int wn   = wid >> 1;
    const int bx   = blockIdx.x;
    const long mBase = (long)blockIdx.y * 128;

    const int  rowA = tid & 127;
    const int  kfA  = (tid >> 7) * 16;
    const int  k2A  = kfA >> 1;
    const long gRowA = mBase + rowA;
    const bool okA   = gRowA < M;
    const float* Ag  = A + gRowA * F_IN + kfA;

    const int krB  = tid >> 4;
    const int colB = (tid & 15) * 8;
    const unsigned* Wp = g_w1p + (long)bx * 128 + colB;

    float fa[16];
    uint4 ub0, ub1;

    if (okA) {
#pragma unroll
        for (int j = 0; j < 4; j++) *(float4*)&fa[j * 4] = *(const float4*)(Ag + j * 4);
    } else {
#pragma unroll
        for (int j = 0; j < 16; j++) fa[j] = 0.f;
    }
    ub0 = *(const uint4*)(Wp + (long)krB * F_HID);
    ub1 = *(const uint4*)(Wp + (long)krB * F_HID + 4);

#pragma unroll
    for (int j = 0; j < 8; j++) As2[0][k2A + j][rowA] = packh2(fa[2 * j], fa[2 * j + 1]);
    *(uint4*)&Bs2[0][krB][colB]     = ub0;
    *(uint4*)&Bs2[0][krB][colB + 4] = ub1;
    __syncthreads();

    float c[4][4][4];
#pragma unroll
    for (int mt = 0; mt < 4; mt++)
#pragma unroll
        for (int nt = 0; nt < 4; nt++)
#pragma unroll
            for (int q = 0; q < 4; q++) c[mt][nt][q] = 0.f;

    int cur = 0;
    const int NITER = F_IN / 32;
    for (int it = 0; it < NITER; ++it) {
        if (it + 1 < NITER) {
            int kf = (it + 1) * 32;
            if (okA) {
#pragma unroll
                for (int j = 0; j < 4; j++) *(float4*)&fa[j * 4] = *(const float4*)(Ag + kf + j * 4);
            }
            ub0 = *(const uint4*)(Wp + (long)(kf / 2 + krB) * F_HID);
            ub1 = *(const uint4*)(Wp + (long)(kf / 2 + krB) * F_HID + 4);
        }

#pragma unroll
        for (int kk = 0; kk < 16; kk += 8) {
            const int k2q = kk + (lane & 3);
            const int p   = lane >> 2;
            unsigned afr[4][4], bfr[4][2];
#pragma unroll
            for (int mt = 0; mt < 4; mt++) {
                int r = wm * 64 + mt * 16 + p;
                afr[mt][0] = As2[cur][k2q][r];
                afr[mt][1] = As2[cur][k2q][r + 8];
                afr[mt][2] = As2[cur][k2q + 4][r];
                afr[mt][3] = As2[cur][k2q + 4][r + 8];
            }
#pragma unroll
            for (int nt = 0; nt < 4; nt++) {
                int cc = wn * 32 + nt * 8 + p;
                bfr[nt][0] = Bs2[cur][k2q][cc];
                bfr[nt][1] = Bs2[cur][k2q + 4][cc];
            }
#pragma unroll
            for (int mt = 0; mt < 4; mt++)
#pragma unroll
                for (int nt = 0; nt < 4; nt++)
                    mma16(c[mt][nt], afr[mt], bfr[nt]);
        }

        if (it + 1 < NITER) {
            int nxt = cur ^ 1;
#pragma unroll
            for (int j = 0; j < 8; j++) As2[nxt][k2A + j][rowA] = packh2(fa[2 * j], fa[2 * j + 1]);
            *(uint4*)&Bs2[nxt][krB][colB]     = ub0;
            *(uint4*)&Bs2[nxt][krB][colB + 4] = ub1;
            __syncthreads();
            cur = nxt;
        }
    }

    const int p  = lane >> 2;
    const int q2 = (lane & 3) * 2;
#pragma unroll
    for (int mt = 0; mt < 4; mt++) {
        long r0 = mBase + wm * 64 + mt * 16 + p;
        long r1 = r0 + 8;
        if (r0 < M) {
#pragma unroll
            for (int nt = 0; nt < 4; nt++) {
                int col = bx * 128 + wn * 32 + nt * 8 + q2;
                g_hh[r0 * (F_HID/2) + (col >> 1)] = packh2(c[mt][nt][0], c[mt][nt][1]);
            }
        }
        if (r1 < M) {
#pragma unroll
            for (int nt = 0; nt < 4; nt++) {
                int col = bx * 128 + wn * 32 + nt * 8 + q2;
                g_hh[r1 * (F_HID/2) + (col >> 1)] = packh2(c[mt][nt][2], c[mt][nt][3]);
            }
        }
    }
}

// ---------------- agg1 + bias + relu + GEMM2 fused (dinv[j] applied at gather) ----------------
__global__ __launch_bounds__(256) void k_agg1(const float* __restrict__ b1, int n) {
    __shared__ float w2s[F_OUT * F_HID];   // 40 KB
    __shared__ float hsm[F_HID];
    __shared__ float pA[128], pB[128];
    __shared__ int   jsm[256];
    __shared__ float djs[256];
    int tid = threadIdx.x;
    for (int idx = tid; idx < F_OUT * F_HID; idx += 256) w2s[idx] = g_w2t[idx];
    __syncthreads();

    const int half = tid >> 7;
    const int f2   = tid & 127;
    const int lane = tid & 31, w = tid >> 5;
    const float bias0 = b1[2 * f2];
    const float bias1 = b1[2 * f2 + 1];

    for (int i = blockIdx.x; i < n; i += gridDim.x) {
        int start = g_rowptr[i];
        int end   = g_rowptr[i + 1];
        float dvi = g_dinv[i];

        float acc0 = 0.f, acc1 = 0.f;
        if (half == 0) {   // self-loop: dinv[i] * h[i]
            unsigned u = g_hh[(long)i * 128 + f2];
            __half2 hh = *(__half2*)&u;
            acc0 = dvi * __low2float(hh);
            acc1 = dvi * __high2float(hh);
        }

        for (int base = start; base < end; base += 256) {
            int m = min(256, end - base);
            __syncthreads();
            if (tid < m) {
                int j = g_adj[base + tid];
                jsm[tid] = j;
                djs[tid] = g_dinv[j];
            }
            __syncthreads();
            for (int t = half; t < m; t += 2) {
                long j = jsm[t];
                float d = djs[t];
                unsigned u = g_hh[j * 128 + f2];
                __half2 hh = *(__half2*)&u;
                acc0 = fmaf(d, __low2float(hh), acc0);
                acc1 = fmaf(d, __high2float(hh), acc1);
            }
        }

        if (half == 1) { pA[f2] = acc0; pB[f2] = acc1; }
        __syncthreads();
        if (half == 0) {
            hsm[2 * f2]     = fmaxf(fmaf(acc0 + pA[f2], dvi, bias0), 0.f);
            hsm[2 * f2 + 1] = fmaxf(fmaf(acc1 + pB[f2], dvi, bias1), 0.f);
        }
        __syncthreads();

        // GEMM2: 8 warps x 5 outputs; lane l owns f = l, l+32, ..., l+224
        float hv[8];
#pragma unroll
        for (int k = 0; k < 8; k++) hv[k] = hsm[(k << 5) + lane];
#pragma unroll
        for (int oo = 0; oo < 5; oo++) {
            int o = w * 5 + oo;
            const float* wrow = &w2s[o * F_HID];
            float p = 0.f;
#pragma unroll
            for (int k = 0; k < 8; k++) p = fmaf(hv[k], wrow[(k << 5) + lane], p);
#pragma unroll
            for (int off = 16; off; off >>= 1)
                p += __shfl_xor_sync(0xffffffffu, p, off);
            if (lane == 0) g_h2[(long)i * F_OUT + o] = p * dvi;
        }
    }
}

// ---------------- agg2 + bias + log_softmax ----------------
__global__ __launch_bounds__(256) void k_agg2(const float* __restrict__ b2,
                                              float* __restrict__ outF,
                                              float* __restrict__ outL,
                                              int n, int writeL) {
    int lane = threadIdx.x & 31;
    int wid  = (blockIdx.x * blockDim.x + threadIdx.x) >> 5;
    int nw   = (gridDim.x * blockDim.x) >> 5;
    float bias0 = b2[lane];
    float bias1 = (lane < 8) ? b2[32 + lane] : 0.f;

    for (int i = wid; i < n; i += nw) {
        int start = g_rowptr[i];
        int end   = g_rowptr[i + 1];
        long ib = (long)i * F_OUT;
        float a0 = g_h2[ib + lane];
        float a1 = (lane < 8) ? g_h2[ib + 32 + lane] : 0.f;
        for (int e = start; e < end; e++) {
            int j = g_adj[e];
            long jb = (long)j * F_OUT;
            a0 += g_h2[jb + lane];
            if (lane < 8) a1 += g_h2[jb + 32 + lane];
        }
        float dv = g_dinv[i];
        float f0 = fmaf(a0, dv, bias0);
        float f1 = (lane < 8) ? fmaf(a1, dv, bias1) : -INFINITY;
        outF[ib + lane] = f0;
        if (lane < 8) outF[ib + 32 + lane] = f1;

        if (writeL) {
            float mx = fmaxf(f0, f1);
#pragma unroll
            for (int off = 16; off; off >>= 1)
                mx = fmaxf(mx, __shfl_xor_sync(0xffffffffu, mx, off));
            float s = expf(f0 - mx) + ((lane < 8) ? expf(f1 - mx) : 0.f);
#pragma unroll
            for (int off = 16; off; off >>= 1)
                s += __shfl_xor_sync(0xffffffffu, s, off);
            float lse = mx + logf(s);
            outL[ib + lane] = f0 - lse;
            if (lane < 8) outL[ib + 32 + lane] = f1 - lse;
        }
    }
}

// ---------------- launch ----------------
extern "C" void kernel_launch(void* const* d_in, const int* in_sizes, int n_in,
                              void* d_out, int out_size) {
    const float* x  = (const float*)d_in[0];
    const void*  ei = d_in[1];
    const float* W1 = (const float*)d_in[2];
    const float* b1 = (const float*)d_in[3];
    const float* W2 = (const float*)d_in[4];
    const float* b2 = (const float*)d_in[5];

    int n = in_sizes[0] / F_IN;
    int E = in_sizes[1] / 2;

    float* out = (float*)d_out;
    int half = n * F_OUT;
    float* outF = out;
    float* outL = out;
    int writeL = 0;
    if (out_size >= 2 * half) { outL = out + half; writeL = 1; }

    int nb  = (n + 1023) >> 10;
    int nbI = (n + 255) / 256;

    // One-time stream/event creation (happens on the correctness call, which
    // precedes graph capture; identical GPU work is issued on every call).
    static cudaStream_t sB = 0;
    static cudaEvent_t  evF = 0, evJ = 0;
    if (!sB) {
        cudaStreamCreateWithFlags(&sB, cudaStreamNonBlocking);
        cudaEventCreateWithFlags(&evF, cudaEventDisableTiming);
        cudaEventCreateWithFlags(&evJ, cudaEventDisableTiming);
    }

    // ---- fork: GEMM chain (stream sB) runs concurrently with edge chain (legacy) ----
    cudaEventRecord(evF, 0);
    cudaStreamWaitEvent(sB, evF, 0);

    // stream sB: pack W1 -> GEMM1 (depends only on x, W1)
    k_w1p<<<256, 256, 0, sB>>>(W1);
    dim3 g1(2, (n + 127) / 128);
    k_gemm1_h<<<g1, 256, 0, sB>>>(x, n);
    cudaEventRecord(evJ, sB);

    // legacy stream: edge chain
    k_prepA  <<<nbI + 40, 256>>>(n, nbI, W2);
    k_detect <<<64, 256>>>((const long long*)ei, E, n);
    k_convert<<<2048, 256>>>(ei, E, n);
    k_dinv   <<<nbI, 256>>>(n);
    k_scan1  <<<nb, 1024>>>(n);
    k_scan2  <<<1, 256>>>(nb);
    k_scan3  <<<nbI, 256>>>(n, E);
    k_fill   <<<2048, 256>>>(E);

    // ---- join: agg1 needs both chains ----
    cudaStreamWaitEvent(0, evJ, 0);
    k_agg1<<<4096, 256>>>(b1, n);
    k_agg2<<<2048, 256>>>(b2, outF, outL, n, writeL);
}

// round 13
// speedup vs baseline: 1.1028x; 1.0615x over previous
#include <cuda_runtime.h>
#include <cuda_bf16.h>
#include <cuda_fp16.h>
#include <stdint.h>
#include <math.h>

// Problem constants (fixed by the reference)
#define F_IN   512
#define F_HID  256
#define F_OUT  40
#define MAXN   100000
#define MAXE   3200000

// ---------------- scratch (device globals; no runtime allocation) ----------------
__device__ int   g_is32;
__device__ int   g_eidx[2 * MAXE];
__device__ int   g_deg[MAXN];
__device__ int   g_cnt[MAXN];
__device__ float g_dinv[MAXN];
__device__ int   g_rowptr[MAXN + 1];
__device__ int   g_cursor[MAXN];
__device__ int   g_adj[MAXE];
__device__ int   g_part[256];
__device__ float g_w2t[F_OUT * F_HID];
__device__ unsigned g_w1p[(F_IN / 2) * F_HID];    // W1 packed half2 along k: [k2][n]
__device__ unsigned g_hh[(long)MAXN * (F_HID/2)]; // h half2-packed (x@W1, UNSCALED)
__device__ float g_h2[(long)MAXN * F_OUT];        // h2_s = dinv[i] * (relu(...) @ W2)

// ---------------- helpers ----------------
__device__ __forceinline__ unsigned packh2(float lo, float hi) {
    __half2 h = __floats2half2_rn(lo, hi);
    return *(unsigned*)&h;
}

// ---------------- prep A (edge-chain stream): init counters + transpose W2 ----------------
__global__ void k_prepA(int n, int nbI, const float* __restrict__ W2) {
    int b = blockIdx.x;
    int t = threadIdx.x;
    if (b < nbI) {
        int i = b * 256 + t;
        if (i < n) { g_deg[i] = 1; g_cnt[i] = 0; }
        if (b == 0 && t == 0) g_is32 = 0;
    } else {
        int idx = (b - nbI) * 256 + t;          // < F_OUT*F_HID
        int o = idx / F_HID, f = idx % F_HID;
        g_w2t[idx] = W2[f * F_OUT + o];
    }
}

// ---------------- prep B (gemm stream): pack W1 ----------------
__global__ void k_w1p(const float* __restrict__ W1) {
    int idx = blockIdx.x * blockDim.x + threadIdx.x;   // < 256*256
    int k2 = idx >> 8;
    int nn = idx & 255;
    g_w1p[idx] = packh2(W1[(2 * k2) * F_HID + nn], W1[(2 * k2 + 1) * F_HID + nn]);
}

// Sample first 64K int64 words: any out-of-range value => data is really int32.
__global__ void k_detect(const long long* __restrict__ ei, int E, int n) {
    int cnt = min(E, 1 << 16);
    int bad = 0;
    for (int e = blockIdx.x * blockDim.x + threadIdx.x; e < cnt; e += gridDim.x * blockDim.x) {
        long long v = ei[e];
        if (v < 0 || v >= n) bad = 1;
    }
    if (__syncthreads_or(bad)) {
        if (threadIdx.x == 0) g_is32 = 1;
    }
}

// convert raw -> int32 g_eidx, with fused degree histogram
__global__ void k_convert(const void* __restrict__ ei_raw, int E, int n) {
    int is32 = g_is32;
    const int*       e32 = (const int*)ei_raw;
    const long long* e64 = (const long long*)ei_raw;
    for (long e = blockIdx.x * blockDim.x + threadIdx.x; e < 2L * E; e += (long)gridDim.x * blockDim.x) {
        long long v = is32 ? (long long)e32[e] : e64[e];
        if (v < 0) v = 0;
        if (v >= n) v = n - 1;
        int vi = (int)v;
        g_eidx[e] = vi;
        if (e < E) atomicAdd(&g_cnt[vi], 1);   // row counts
        else       atomicAdd(&g_deg[vi], 1);   // col degrees
    }
}

__global__ void k_dinv(int n) {
    int i = blockIdx.x * blockDim.x + threadIdx.x;
    if (i < n) g_dinv[i] = rsqrtf((float)g_deg[i]);
}

// ---------------- CSR build ----------------
__global__ void k_scan1(int n) {
    __shared__ int s[1024];
    int tid = threadIdx.x;
    int idx = blockIdx.x * 1024 + tid;
    int v = (idx < n) ? g_cnt[idx] : 0;
    s[tid] = v;
    __syncthreads();
    for (int off = 1; off < 1024; off <<= 1) {
        int t = (tid >= off) ? s[tid - off] : 0;
        __syncthreads();
        s[tid] += t;
        __syncthreads();
    }
    if (idx < n) g_rowptr[idx] = s[tid] - v;
    if (tid == 1023) g_part[blockIdx.x] = s[1023];
}

__global__ void k_scan2(int nb) {
    __shared__ int s[256];
    int tid = threadIdx.x;
    int v = (tid < nb) ? g_part[tid] : 0;
    s[tid] = v;
    __syncthreads();
    for (int off = 1; off < 256; off <<= 1) {
        int t = (tid >= off) ? s[tid - off] : 0;
        __syncthreads();
        s[tid] += t;
        __syncthreads();
    }
    if (tid < nb) g_part[tid] = s[tid] - v;
}

__global__ void k_scan3(int n, int E) {
    int i = blockIdx.x * blockDim.x + threadIdx.x;
    if (i < n) {
        int rp = g_rowptr[i] + g_part[i >> 10];
        g_rowptr[i] = rp;
        g_cursor[i] = rp;
    }
    if (blockIdx.x == 0 && threadIdx.x == 0) g_rowptr[n] = E;
}

__global__ void k_fill(int E) {
    for (int e = blockIdx.x * blockDim.x + threadIdx.x; e < E; e += gridDim.x * blockDim.x) {
        int r = g_eidx[e];
        int c = g_eidx[E + e];
        int pos = atomicAdd(&g_cursor[r], 1);
        g_adj[pos] = c;
    }
}

// ---------------- fp16 tensor-core GEMM1 (mma.sync.m16n8k16), NO dinv scaling ----------------
__device__ __forceinline__ void mma16(float c[4], const unsigned a[4], const unsigned b[2]) {
    asm volatile(
        "mma.sync.aligned.m16n8k16.row.col.f32.f16.f16.f32 "
        "{%0,%1,%2,%3}, {%4,%5,%6,%7}, {%8,%9}, {%0,%1,%2,%3};"
        : "+f"(c[0]), "+f"(c[1]), "+f"(c[2]), "+f"(c[3])
        : "r"(a[0]), "r"(a[1]), "r"(a[2]), "r"(a[3]), "r"(b[0]), "r"(b[1]));
}

#define SPAD 136

__global__ __launch_bounds__(256, 2) void k_gemm1_h(const float* __restrict__ A, int M) {
    __shared__ unsigned As2[2][16][SPAD];
    __shared__ unsigned Bs2[2][16][SPAD];

    const int tid  = threadIdx.x;
    const int lane = tid & 31;
    const int wid  = tid >> 5;
    const int wm   = wid & 1;
    const int wn   = wid >> 1;
    const int bx   = blockIdx.x;
    const long mBase = (long)blockIdx.y * 128;

    const int  rowA = tid & 127;
    const int  kfA  = (tid >> 7) * 16;
    const int  k2A  = kfA >> 1;
    const long gRowA = mBase + rowA;
    const bool okA   = gRowA < M;
    const float* Ag  = A + gRowA * F_IN + kfA;

    const int krB  = tid >> 4;
    const int colB = (tid & 15) * 8;
    const unsigned* Wp = g_w1p + (long)bx * 128 + colB;

    float fa[16];
    uint4 ub0, ub1;

    if (okA) {
#pragma unroll
        for (int j = 0; j < 4; j++) *(float4*)&fa[j * 4] = *(const float4*)(Ag + j * 4);
    } else {
#pragma unroll
        for (int j = 0; j < 16; j++) fa[j] = 0.f;
    }
    ub0 = *(const uint4*)(Wp + (long)krB * F_HID);
    ub1 = *(const uint4*)(Wp + (long)krB * F_HID + 4);

#pragma unroll
    for (int j = 0; j < 8; j++) As2[0][k2A + j][rowA] = packh2(fa[2 * j], fa[2 * j + 1]);
    *(uint4*)&Bs2[0][krB][colB]     = ub0;
    *(uint4*)&Bs2[0][krB][colB + 4] = ub1;
    __syncthreads();

    float c[4][4][4];
#pragma unroll
    for (int mt = 0; mt < 4; mt++)
#pragma unroll
        for (int nt = 0; nt < 4; nt++)
#pragma unroll
            for (int q = 0; q < 4; q++) c[mt][nt][q] = 0.f;

    int cur = 0;
    const int NITER = F_IN / 32;
    for (int it = 0; it < NITER; ++it) {
        if (it + 1 < NITER) {
            int kf = (it + 1) * 32;
            if (okA) {
#pragma unroll
                for (int j = 0; j < 4; j++) *(float4*)&fa[j * 4] = *(const float4*)(Ag + kf + j * 4);
            }
            ub0 = *(const uint4*)(Wp + (long)(kf / 2 + krB) * F_HID);
            ub1 = *(const uint4*)(Wp + (long)(kf / 2 + krB) * F_HID + 4);
        }

#pragma unroll
        for (int kk = 0; kk < 16; kk += 8) {
            const int k2q = kk + (lane & 3);
            const int p   = lane >> 2;
            unsigned afr[4][4], bfr[4][2];
#pragma unroll
            for (int mt = 0; mt < 4; mt++) {
                int r = wm * 64 + mt * 16 + p;
                afr[mt][0] = As2[cur][k2q][r];
                afr[mt][1] = As2[cur][k2q][r + 8];
                afr[mt][2] = As2[cur][k2q + 4][r];
                afr[mt][3] = As2[cur][k2q + 4][r + 8];
            }
#pragma unroll
            for (int nt = 0; nt < 4; nt++) {
                int cc = wn * 32 + nt * 8 + p;
                bfr[nt][0] = Bs2[cur][k2q][cc];
                bfr[nt][1] = Bs2[cur][k2q + 4][cc];
            }
#pragma unroll
            for (int mt = 0; mt < 4; mt++)
#pragma unroll
                for (int nt = 0; nt < 4; nt++)
                    mma16(c[mt][nt], afr[mt], bfr[nt]);
        }

        if (it + 1 < NITER) {
            int nxt = cur ^ 1;
#pragma unroll
            for (int j = 0; j < 8; j++) As2[nxt][k2A + j][rowA] = packh2(fa[2 * j], fa[2 * j + 1]);
            *(uint4*)&Bs2[nxt][krB][colB]     = ub0;
            *(uint4*)&Bs2[nxt][krB][colB + 4] = ub1;
            __syncthreads();
            cur = nxt;
        }
    }

    const int p  = lane >> 2;
    const int q2 = (lane & 3) * 2;
#pragma unroll
    for (int mt = 0; mt < 4; mt++) {
        long r0 = mBase + wm * 64 + mt * 16 + p;
        long r1 = r0 + 8;
        if (r0 < M) {
#pragma unroll
            for (int nt = 0; nt < 4; nt++) {
                int col = bx * 128 + wn * 32 + nt * 8 + q2;
                g_hh[r0 * (F_HID/2) + (col >> 1)] = packh2(c[mt][nt][0], c[mt][nt][1]);
            }
        }
        if (r1 < M) {
#pragma unroll
            for (int nt = 0; nt < 4; nt++) {
                int col = bx * 128 + wn * 32 + nt * 8 + q2;
                g_hh[r1 * (F_HID/2) + (col >> 1)] = packh2(c[mt][nt][2], c[mt][nt][3]);
            }
        }
    }
}

// ---------------- agg1 + bias + relu + GEMM2 fused (warp-per-edge) ----------------
// 8 warps stride the edge list; each warp pulls a whole 512B h-row with one
// LDG.128 (lane l owns features 8l..8l+7), accumulates dinv[j]-scaled partials
// in 8 fp32 regs, then block-combines via smem. No per-chunk syncs or staging.
__global__ __launch_bounds__(256) void k_agg1(const float* __restrict__ b1, int n) {
    __shared__ float w2s[F_OUT * F_HID];   // 40 KB
    __shared__ float part[8][F_HID];       // 8 KB
    __shared__ float hsm[F_HID];
    int tid = threadIdx.x;
    for (int idx = tid; idx < F_OUT * F_HID; idx += 256) w2s[idx] = g_w2t[idx];
    __syncthreads();

    const int lane = tid & 31;
    const int w    = tid >> 5;
    const float biasf = b1[tid];

    for (int i = blockIdx.x; i < n; i += gridDim.x) {
        int start = g_rowptr[i];
        int end   = g_rowptr[i + 1];
        float dvi = g_dinv[i];

        float acc[8];
#pragma unroll
        for (int k = 0; k < 8; k++) acc[k] = 0.f;

        // self-loop on warp 0: dinv[i] * h[i]
        if (w == 0) {
            uint4 u = *(const uint4*)(g_hh + (long)i * 128 + lane * 4);
            __half2 h0 = *(__half2*)&u.x, h1 = *(__half2*)&u.y;
            __half2 h2 = *(__half2*)&u.z, h3 = *(__half2*)&u.w;
            acc[0] = dvi * __low2float(h0); acc[1] = dvi * __high2float(h0);
            acc[2] = dvi * __low2float(h1); acc[3] = dvi * __high2float(h1);
            acc[4] = dvi * __low2float(h2); acc[5] = dvi * __high2float(h2);
            acc[6] = dvi * __low2float(h3); acc[7] = dvi * __high2float(h3);
        }

        for (int e = start + w; e < end; e += 8) {
            int   j = g_adj[e];        // broadcast
            float d = g_dinv[j];       // broadcast
            uint4 u = *(const uint4*)(g_hh + (long)j * 128 + lane * 4);
            __half2 h0 = *(__half2*)&u.x, h1 = *(__half2*)&u.y;
            __half2 h2 = *(__half2*)&u.z, h3 = *(__half2*)&u.w;
            acc[0] = fmaf(d, __low2float(h0), acc[0]);
            acc[1] = fmaf(d, __high2float(h0), acc[1]);
            acc[2] = fmaf(d, __low2float(h1), acc[2]);
            acc[3] = fmaf(d, __high2float(h1), acc[3]);
            acc[4] = fmaf(d, __low2float(h2), acc[4]);
            acc[5] = fmaf(d, __high2float(h2), acc[5]);
            acc[6] = fmaf(d, __low2float(h3), acc[6]);
            acc[7] = fmaf(d, __high2float(h3), acc[7]);
        }

        *(float4*)&part[w][lane * 8]     = make_float4(acc[0], acc[1], acc[2], acc[3]);
        *(float4*)&part[w][lane * 8 + 4] = make_float4(acc[4], acc[5], acc[6], acc[7]);
        __syncthreads();

        // reduce 8 partials for feature f = tid, then bias+relu
        {
            float s = part[0][tid];
#pragma unroll
            for (int ww = 1; ww < 8; ww++) s += part[ww][tid];
            hsm[tid] = fmaxf(fmaf(s, dvi, biasf), 0.f);
        }
        __syncthreads();

        // GEMM2: 8 warps x 5 outputs; lane l owns f = l, l+32, ..., l+224
        float hv[8];
#pragma unroll
        for (int k = 0; k < 8; k++) hv[k] = hsm[(k << 5) + lane];
#pragma unroll
        for (int oo = 0; oo < 5; oo++) {
            int o = w * 5 + oo;
            const float* wrow = &w2s[o * F_HID];
            float p = 0.f;
#pragma unroll
            for (int k = 0; k < 8; k++) p = fmaf(hv[k], wrow[(k << 5) + lane], p);
#pragma unroll
            for (int off = 16; off; off >>= 1)
                p += __shfl_xor_sync(0xffffffffu, p, off);
            if (lane == 0) g_h2[(long)i * F_OUT + o] = p * dvi;
        }
        __syncthreads();   // protect part/hsm before next node
    }
}

// ---------------- agg2 + bias + log_softmax ----------------
__global__ __launch_bounds__(256) void k_agg2(const float* __restrict__ b2,
                                              float* __restrict__ outF,
                                              float* __restrict__ outL,
                                              int n, int writeL) {
    int lane = threadIdx.x & 31;
    int wid  = (blockIdx.x * blockDim.x + threadIdx.x) >> 5;
    int nw   = (gridDim.x * blockDim.x) >> 5;
    float bias0 = b2[lane];
    float bias1 = (lane < 8) ? b2[32 + lane] : 0.f;

    for (int i = wid; i < n; i += nw) {
        int start = g_rowptr[i];
        int end   = g_rowptr[i + 1];
        long ib = (long)i * F_OUT;
        float a0 = g_h2[ib + lane];
        float a1 = (lane < 8) ? g_h2[ib + 32 + lane] : 0.f;
        for (int e = start; e < end; e++) {
            int j = g_adj[e];
            long jb = (long)j * F_OUT;
            a0 += g_h2[jb + lane];
            if (lane < 8) a1 += g_h2[jb + 32 + lane];
        }
        float dv = g_dinv[i];
        float f0 = fmaf(a0, dv, bias0);
        float f1 = (lane < 8) ? fmaf(a1, dv, bias1) : -INFINITY;
        outF[ib + lane] = f0;
        if (lane < 8) outF[ib + 32 + lane] = f1;

        if (writeL) {
            float mx = fmaxf(f0, f1);
#pragma unroll
            for (int off = 16; off; off >>= 1)
                mx = fmaxf(mx, __shfl_xor_sync(0xffffffffu, mx, off));
            float s = expf(f0 - mx) + ((lane < 8) ? expf(f1 - mx) : 0.f);
#pragma unroll
            for (int off = 16; off; off >>= 1)
                s += __shfl_xor_sync(0xffffffffu, s, off);
            float lse = mx + logf(s);
            outL[ib + lane] = f0 - lse;
            if (lane < 8) outL[ib + 32 + lane] = f1 - lse;
        }
    }
}

// ---------------- launch ----------------
extern "C" void kernel_launch(void* const* d_in, const int* in_sizes, int n_in,
                              void* d_out, int out_size) {
    const float* x  = (const float*)d_in[0];
    const void*  ei = d_in[1];
    const float* W1 = (const float*)d_in[2];
    const float* b1 = (const float*)d_in[3];
    const float* W2 = (const float*)d_in[4];
    const float* b2 = (const float*)d_in[5];

    int n = in_sizes[0] / F_IN;
    int E = in_sizes[1] / 2;

    float* out = (float*)d_out;
    int half = n * F_OUT;
    float* outF = out;
    float* outL = out;
    int writeL = 0;
    if (out_size >= 2 * half) { outL = out + half; writeL = 1; }

    int nb  = (n + 1023) >> 10;
    int nbI = (n + 255) / 256;

    // One-time stream/event creation (happens on the correctness call, which
    // precedes graph capture; identical GPU work is issued on every call).
    static cudaStream_t sB = 0;
    static cudaEvent_t  evF = 0, evJ = 0;
    if (!sB) {
        cudaStreamCreateWithFlags(&sB, cudaStreamNonBlocking);
        cudaEventCreateWithFlags(&evF, cudaEventDisableTiming);
        cudaEventCreateWithFlags(&evJ, cudaEventDisableTiming);
    }

    // ---- fork: GEMM chain (stream sB) runs concurrently with edge chain (legacy) ----
    cudaEventRecord(evF, 0);
    cudaStreamWaitEvent(sB, evF, 0);

    // stream sB: pack W1 -> GEMM1 (depends only on x, W1)
    k_w1p<<<256, 256, 0, sB>>>(W1);
    dim3 g1(2, (n + 127) / 128);
    k_gemm1_h<<<g1, 256, 0, sB>>>(x, n);
    cudaEventRecord(evJ, sB);

    // legacy stream: edge chain
    k_prepA  <<<nbI + 40, 256>>>(n, nbI, W2);
    k_detect <<<64, 256>>>((const long long*)ei, E, n);
    k_convert<<<2048, 256>>>(ei, E, n);
    k_dinv   <<<nbI, 256>>>(n);
    k_scan1  <<<nb, 1024>>>(n);
    k_scan2  <<<1, 256>>>(nb);
    k_scan3  <<<nbI, 256>>>(n, E);
    k_fill   <<<2048, 256>>>(E);

    // ---- join: agg1 needs both chains ----
    cudaStreamWaitEvent(0, evJ, 0);
    k_agg1<<<4096, 256>>>(b1, n);
    k_agg2<<<2048, 256>>>(b2, outF, outL, n, writeL);
}

// round 15
// speedup vs baseline: 1.4297x; 1.2965x over previous
#include <cuda_runtime.h>
#include <cuda_bf16.h>
#include <cuda_fp16.h>
#include <stdint.h>
#include <math.h>

// Problem constants (fixed by the reference)
#define F_IN   512
#define F_HID  256
#define F_OUT  40
#define MAXN   100000
#define MAXE   3200000

// ---------------- scratch (device globals; no runtime allocation) ----------------
__device__ int   g_is32;
__device__ int   g_eidx[2 * MAXE];
__device__ int   g_deg[MAXN];
__device__ int   g_cnt[MAXN];
__device__ float g_dinv[MAXN];
__device__ unsigned g_dinvh[MAXN];                // dinv as half2(d,d)
__device__ int   g_rowptr[MAXN + 1];
__device__ int   g_cursor[MAXN];
__device__ int   g_adj[MAXE];
__device__ int   g_part[256];
__device__ unsigned g_w2h[F_OUT * (F_HID / 2)];   // W2^T packed half2: [o][f2]
__device__ unsigned g_w1p[(F_IN / 2) * F_HID];    // W1 packed half2 along k: [k2][n]
__device__ unsigned g_hh[(long)MAXN * (F_HID/2)]; // h half2-packed (x@W1, UNSCALED)
__device__ float g_h2[(long)MAXN * F_OUT];        // h2_s = dinv[i] * (relu(...) @ W2)

// ---------------- helpers ----------------
__device__ __forceinline__ unsigned packh2(float lo, float hi) {
    __half2 h = __floats2half2_rn(lo, hi);
    return *(unsigned*)&h;
}

// ---------------- prep A (edge-chain stream): init counters + pack W2 ----------------
// blocks [0, nbI): init; [nbI, nbI+20): w2h (40*128 = 5120 elems)
__global__ void k_prepA(int n, int nbI, const float* __restrict__ W2) {
    int b = blockIdx.x;
    int t = threadIdx.x;
    if (b < nbI) {
        int i = b * 256 + t;
        if (i < n) { g_deg[i] = 1; g_cnt[i] = 0; }
        if (b == 0 && t == 0) g_is32 = 0;
    } else {
        int idx = (b - nbI) * 256 + t;          // < 5120
        int o = idx >> 7, f2 = idx & 127;
        g_w2h[idx] = packh2(W2[(2 * f2) * F_OUT + o], W2[(2 * f2 + 1) * F_OUT + o]);
    }
}

// ---------------- prep B (gemm stream): pack W1 ----------------
__global__ void k_w1p(const float* __restrict__ W1) {
    int idx = blockIdx.x * blockDim.x + threadIdx.x;   // < 256*256
    int k2 = idx >> 8;
    int nn = idx & 255;
    g_w1p[idx] = packh2(W1[(2 * k2) * F_HID + nn], W1[(2 * k2 + 1) * F_HID + nn]);
}

// Sample first 64K int64 words: any out-of-range value => data is really int32.
__global__ void k_detect(const long long* __restrict__ ei, int E, int n) {
    int cnt = min(E, 1 << 16);
    int bad = 0;
    for (int e = blockIdx.x * blockDim.x + threadIdx.x; e < cnt; e += gridDim.x * blockDim.x) {
        long long v = ei[e];
        if (v < 0 || v >= n) bad = 1;
    }
    if (__syncthreads_or(bad)) {
        if (threadIdx.x == 0) g_is32 = 1;
    }
}

// convert raw -> int32 g_eidx, with fused degree histogram
__global__ void k_convert(const void* __restrict__ ei_raw, int E, int n) {
    int is32 = g_is32;
    const int*       e32 = (const int*)ei_raw;
    const long long* e64 = (const long long*)ei_raw;
    for (long e = blockIdx.x * blockDim.x + threadIdx.x; e < 2L * E; e += (long)gridDim.x * blockDim.x) {
        long long v = is32 ? (long long)e32[e] : e64[e];
        if (v < 0) v = 0;
        if (v >= n) v = n - 1;
        int vi = (int)v;
        g_eidx[e] = vi;
        if (e < E) atomicAdd(&g_cnt[vi], 1);   // row counts
        else       atomicAdd(&g_deg[vi], 1);   // col degrees
    }
}

__global__ void k_dinv(int n) {
    int i = blockIdx.x * blockDim.x + threadIdx.x;
    if (i < n) {
        float d = rsqrtf((float)g_deg[i]);
        g_dinv[i]  = d;
        g_dinvh[i] = packh2(d, d);
    }
}

// ---------------- CSR build ----------------
__global__ void k_scan1(int n) {
    __shared__ int s[1024];
    int tid = threadIdx.x;
    int idx = blockIdx.x * 1024 + tid;
    int v = (idx < n) ? g_cnt[idx] : 0;
    s[tid] = v;
    __syncthreads();
    for (int off = 1; off < 1024; off <<= 1) {
        int t = (tid >= off) ? s[tid - off] : 0;
        __syncthreads();
        s[tid] += t;
        __syncthreads();
    }
    if (idx < n) g_rowptr[idx] = s[tid] - v;
    if (tid == 1023) g_part[blockIdx.x] = s[1023];
}

__global__ void k_scan2(int nb) {
    __shared__ int s[256];
    int tid = threadIdx.x;
    int v = (tid < nb) ? g_part[tid] : 0;
    s[tid] = v;
    __syncthreads();
    for (int off = 1; off < 256; off <<= 1) {
        int t = (tid >= off) ? s[tid - off] : 0;
        __syncthreads();
        s[tid] += t;
        __syncthreads();
    }
    if (tid < nb) g_part[tid] = s[tid] - v;
}

__global__ void k_scan3(int n, int E) {
    int i = blockIdx.x * blockDim.x + threadIdx.x;
    if (i < n) {
        int rp = g_rowptr[i] + g_part[i >> 10];
        g_rowptr[i] = rp;
        g_cursor[i] = rp;
    }
    if (blockIdx.x == 0 && threadIdx.x == 0) g_rowptr[n] = E;
}

__global__ void k_fill(int E) {
    for (int e = blockIdx.x * blockDim.x + threadIdx.x; e < E; e += gridDim.x * blockDim.x) {
        int r = g_eidx[e];
        int c = g_eidx[E + e];
        int pos = atomicAdd(&g_cursor[r], 1);
        g_adj[pos] = c;
    }
}

// ---------------- fp16 tensor-core GEMM1 (mma.sync.m16n8k16), NO dinv scaling ----------------
__device__ __forceinline__ void mma16(float c[4], const unsigned a[4], const unsigned b[2]) {
    asm volatile(
        "mma.sync.aligned.m16n8k16.row.col.f32.f16.f16.f32 "
        "{%0,%1,%2,%3}, {%4,%5,%6,%7}, {%8,%9}, {%0,%1,%2,%3};"
        : "+f"(c[0]), "+f"(c[1]), "+f"(c[2]), "+f"(c[3])
        : "r"(a[0]), "r"(a[1]), "r"(a[2]), "r"(a[3]), "r"(b[0]), "r"(b[1]));
}

#define SPAD 136

__global__ __launch_bounds__(256, 2) void k_gemm1_h(const float* __restrict__ A, int M) {
    __shared__ unsigned As2[2][16][SPAD];
    __shared__ unsigned Bs2[2][16][SPAD];

    const int tid  = threadIdx.x;
    const int lane = tid & 31;
    const int wid  = tid >> 5;
    const int wm   = wid & 1;
    const int wn   = wid >> 1;
    const int bx   = blockIdx.x;
    const long mBase = (long)blockIdx.y * 128;

    const int  rowA = tid & 127;
    const int  kfA  = (tid >> 7) * 16;
    const int  k2A  = kfA >> 1;
    const long gRowA = mBase + rowA;
    const bool okA   = gRowA < M;
    const float* Ag  = A + gRowA * F_IN + kfA;

    const int krB  = tid >> 4;
    const int colB = (tid & 15) * 8;
    const unsigned* Wp = g_w1p + (long)bx * 128 + colB;

    float fa[16];
    uint4 ub0, ub1;

    if (okA) {
#pragma unroll
        for (int j = 0; j < 4; j++) *(float4*)&fa[j * 4] = *(const float4*)(Ag + j * 4);
    } else {
#pragma unroll
        for (int j = 0; j < 16; j++) fa[j] = 0.f;
    }
    ub0 = *(const uint4*)(Wp + (long)krB * F_HID);
    ub1 = *(const uint4*)(Wp + (long)krB * F_HID + 4);

#pragma unroll
    for (int j = 0; j < 8; j++) As2[0][k2A + j][rowA] = packh2(fa[2 * j], fa[2 * j + 1]);
    *(uint4*)&Bs2[0][krB][colB]     = ub0;
    *(uint4*)&Bs2[0][krB][colB + 4] = ub1;
    __syncthreads();

    float c[4][4][4];
#pragma unroll
    for (int mt = 0; mt < 4; mt++)
#pragma unroll
        for (int nt = 0; nt < 4; nt++)
#pragma unroll
            for (int q = 0; q < 4; q++) c[mt][nt][q] = 0.f;

    int cur = 0;
    const int NITER = F_IN / 32;
    for (int it = 0; it < NITER; ++it) {
        if (it + 1 < NITER) {
            int kf = (it + 1) * 32;
            if (okA) {
#pragma unroll
                for (int j = 0; j < 4; j++) *(float4*)&fa[j * 4] = *(const float4*)(Ag + kf + j * 4);
            }
            ub0 = *(const uint4*)(Wp + (long)(kf / 2 + krB) * F_HID);
            ub1 = *(const uint4*)(Wp + (long)(kf / 2 + krB) * F_HID + 4);
        }

#pragma unroll
        for (int kk = 0; kk < 16; kk += 8) {
            const int k2q = kk + (lane & 3);
            const int p   = lane >> 2;
            unsigned afr[4][4], bfr[4][2];
#pragma unroll
            for (int mt = 0; mt < 4; mt++) {
                int r = wm * 64 + mt * 16 + p;
                afr[mt][0] = As2[cur][k2q][r];
                afr[mt][1] = As2[cur][k2q][r + 8];
                afr[mt][2] = As2[cur][k2q + 4][r];
                afr[mt][3] = As2[cur][k2q + 4][r + 8];
            }
#pragma unroll
            for (int nt = 0; nt < 4; nt++) {
                int cc = wn * 32 + nt * 8 + p;
                bfr[nt][0] = Bs2[cur][k2q][cc];
                bfr[nt][1] = Bs2[cur][k2q + 4][cc];
            }
#pragma unroll
            for (int mt = 0; mt < 4; mt++)
#pragma unroll
                for (int nt = 0; nt < 4; nt++)
                    mma16(c[mt][nt], afr[mt], bfr[nt]);
        }

        if (it + 1 < NITER) {
            int nxt = cur ^ 1;
#pragma unroll
            for (int j = 0; j < 8; j++) As2[nxt][k2A + j][rowA] = packh2(fa[2 * j], fa[2 * j + 1]);
            *(uint4*)&Bs2[nxt][krB][colB]     = ub0;
            *(uint4*)&Bs2[nxt][krB][colB + 4] = ub1;
            __syncthreads();
            cur = nxt;
        }
    }

    const int p  = lane >> 2;
    const int q2 = (lane & 3) * 2;
#pragma unroll
    for (int mt = 0; mt < 4; mt++) {
        long r0 = mBase + wm * 64 + mt * 16 + p;
        long r1 = r0 + 8;
        if (r0 < M) {
#pragma unroll
            for (int nt = 0; nt < 4; nt++) {
                int col = bx * 128 + wn * 32 + nt * 8 + q2;
                g_hh[r0 * (F_HID/2) + (col >> 1)] = packh2(c[mt][nt][0], c[mt][nt][1]);
            }
        }
        if (r1 < M) {
#pragma unroll
            for (int nt = 0; nt < 4; nt++) {
                int col = bx * 128 + wn * 32 + nt * 8 + q2;
                g_hh[r1 * (F_HID/2) + (col >> 1)] = packh2(c[mt][nt][2], c[mt][nt][3]);
            }
        }
    }
}

// ---------------- agg1 + bias + relu + batched tensor-core GEMM2 ----------------
// 16 nodes per batch per block. Per node: 8 warps gather (warp-per-edge, half2
// HFMA2 accumulate, one LDG.128 per edge; lane l owns feature pairs 4l..4l+3),
// combine in fp32, bias+relu, store hs row as fp16 pairs. Every 16 nodes: one
// 16x40x256 mma.m16n8k16 pass (5 warps x 16 k-steps), dinv[i]-scaled writeback.
__global__ __launch_bounds__(256) void k_agg1(const float* __restrict__ b1, int n) {
    __shared__ unsigned sw2[40 * 132];     // W2 half2 [o][f2], padded rows
    __shared__ float2   part2[8][128];
    __shared__ unsigned hsp[16 * 132];     // batch hs half2 [b][f2], padded rows
    const int tid  = threadIdx.x;
    const int lane = tid & 31;
    const int w    = tid >> 5;

    for (int idx = tid; idx < 40 * 128; idx += 256) {
        int row = idx >> 7, col = idx & 127;
        sw2[row * 132 + col] = g_w2h[idx];
    }
    float2 bb = make_float2(0.f, 0.f);
    if (tid < 128) bb = *(const float2*)(b1 + 2 * tid);
    __syncthreads();

    for (int i0 = blockIdx.x * 16; i0 < n; i0 += gridDim.x * 16) {
        // ---- aggregate up to 16 nodes ----
        for (int ib = 0; ib < 16; ib++) {
            int i = i0 + ib;
            if (i >= n) break;              // block-uniform
            int start = g_rowptr[i], end = g_rowptr[i + 1];

            __half2 a0, a1, a2, a3;         // lane owns f2 = 4*lane + {0,1,2,3}
            a0 = a1 = a2 = a3 = __floats2half2_rn(0.f, 0.f);
            if (w == 0) {                   // self-loop: dinv[i]*h[i]
                unsigned du = g_dinvh[i];
                __half2 d2 = *(__half2*)&du;
                uint4 u = *(const uint4*)(g_hh + (long)i * 128 + lane * 4);
                a0 = __hmul2(d2, *(__half2*)&u.x);
                a1 = __hmul2(d2, *(__half2*)&u.y);
                a2 = __hmul2(d2, *(__half2*)&u.z);
                a3 = __hmul2(d2, *(__half2*)&u.w);
            }
#pragma unroll 2
            for (int e = start + w; e < end; e += 8) {
                int j = g_adj[e];           // broadcast
                unsigned du = g_dinvh[j];   // broadcast
                __half2 d2 = *(__half2*)&du;
                uint4 u = *(const uint4*)(g_hh + (long)j * 128 + lane * 4);
                a0 = __hfma2(d2, *(__half2*)&u.x, a0);
                a1 = __hfma2(d2, *(__half2*)&u.y, a1);
                a2 = __hfma2(d2, *(__half2*)&u.z, a2);
                a3 = __hfma2(d2, *(__half2*)&u.w, a3);
            }
            // FIX: store matches load layout (f2 = 4*lane + c)
            {
                float2 f0 = __half22float2(a0), f1 = __half22float2(a1);
                float2 f2v = __half22float2(a2), f3 = __half22float2(a3);
                *(float4*)&part2[w][lane * 4]     = make_float4(f0.x, f0.y, f1.x, f1.y);
                *(float4*)&part2[w][lane * 4 + 2] = make_float4(f2v.x, f2v.y, f3.x, f3.y);
            }
            __syncthreads();

            if (tid < 128) {
                float sx = 0.f, sy = 0.f;
#pragma unroll
                for (int ww = 0; ww < 8; ww++) {
                    float2 p = part2[ww][tid];
                    sx += p.x; sy += p.y;
                }
                float dvi = g_dinv[i];
                float h0 = fmaxf(fmaf(sx, dvi, bb.x), 0.f);
                float h1 = fmaxf(fmaf(sy, dvi, bb.y), 0.f);
                hsp[ib * 132 + tid] = packh2(h0, h1);
            }
            __syncthreads();
        }

        // ---- batched GEMM2: C(16x40) = hs(16x256) @ W2 ----
        if (w < 5) {
            const int r = lane >> 2, q = lane & 3;
            float cc[4] = {0.f, 0.f, 0.f, 0.f};
#pragma unroll
            for (int ks = 0; ks < 16; ks++) {
                int kk2 = ks * 8;
                unsigned a[4], b[2];
                a[0] = hsp[r * 132 + kk2 + q];
                a[1] = hsp[(r + 8) * 132 + kk2 + q];
                a[2] = hsp[r * 132 + kk2 + 4 + q];
                a[3] = hsp[(r + 8) * 132 + kk2 + 4 + q];
                b[0] = sw2[(w * 8 + r) * 132 + kk2 + q];
                b[1] = sw2[(w * 8 + r) * 132 + kk2 + 4 + q];
                mma16(cc, a, b);
            }
            long n0 = (long)i0 + r;
            long n1 = n0 + 8;
            int  o  = w * 8 + q * 2;
            if (n0 < n) {
                float dv = g_dinv[n0];
                *(float2*)(g_h2 + n0 * F_OUT + o) = make_float2(cc[0] * dv, cc[1] * dv);
            }
            if (n1 < n) {
                float dv = g_dinv[n1];
                *(float2*)(g_h2 + n1 * F_OUT + o) = make_float2(cc[2] * dv, cc[3] * dv);
            }
        }
        __syncthreads();   // protect hsp/part2 before next batch
    }
}

// ---------------- agg2 + bias + log_softmax ----------------
__global__ __launch_bounds__(256) void k_agg2(const float* __restrict__ b2,
                                              float* __restrict__ outF,
                                              float* __restrict__ outL,
                                              int n, int writeL) {
    int lane = threadIdx.x & 31;
    int wid  = (blockIdx.x * blockDim.x + threadIdx.x) >> 5;
    int nw   = (gridDim.x * blockDim.x) >> 5;
    float bias0 = b2[lane];
    float bias1 = (lane < 8) ? b2[32 + lane] : 0.f;

    for (int i = wid; i < n; i += nw) {
        int start = g_rowptr[i];
        int end   = g_rowptr[i + 1];
        long ib = (long)i * F_OUT;
        float a0 = g_h2[ib + lane];
        float a1 = (lane < 8) ? g_h2[ib + 32 + lane] : 0.f;
        for (int e = start; e < end; e++) {
            int j = g_adj[e];
            long jb = (long)j * F_OUT;
            a0 += g_h2[jb + lane];
            if (lane < 8) a1 += g_h2[jb + 32 + lane];
        }
        float dv = g_dinv[i];
        float f0 = fmaf(a0, dv, bias0);
        float f1 = (lane < 8) ? fmaf(a1, dv, bias1) : -INFINITY;
        outF[ib + lane] = f0;
        if (lane < 8) outF[ib + 32 + lane] = f1;

        if (writeL) {
            float mx = fmaxf(f0, f1);
#pragma unroll
            for (int off = 16; off; off >>= 1)
                mx = fmaxf(mx, __shfl_xor_sync(0xffffffffu, mx, off));
            float s = expf(f0 - mx) + ((lane < 8) ? expf(f1 - mx) : 0.f);
#pragma unroll
            for (int off = 16; off; off >>= 1)
                s += __shfl_xor_sync(0xffffffffu, s, off);
            float lse = mx + logf(s);
            outL[ib + lane] = f0 - lse;
            if (lane < 8) outL[ib + 32 + lane] = f1 - lse;
        }
    }
}

// ---------------- launch ----------------
extern "C" void kernel_launch(void* const* d_in, const int* in_sizes, int n_in,
                              void* d_out, int out_size) {
    const float* x  = (const float*)d_in[0];
    const void*  ei = d_in[1];
    const float* W1 = (const float*)d_in[2];
    const float* b1 = (const float*)d_in[3];
    const float* W2 = (const float*)d_in[4];
    const float* b2 = (const float*)d_in[5];

    int n = in_sizes[0] / F_IN;
    int E = in_sizes[1] / 2;

    float* out = (float*)d_out;
    int half = n * F_OUT;
    float* outF = out;
    float* outL = out;
    int writeL = 0;
    if (out_size >= 2 * half) { outL = out + half; writeL = 1; }

    int nb  = (n + 1023) >> 10;
    int nbI = (n + 255) / 256;

    // One-time stream/event creation (happens on the correctness call, which
    // precedes graph capture; identical GPU work is issued on every call).
    static cudaStream_t sB = 0;
    static cudaEvent_t  evF = 0, evJ = 0;
    if (!sB) {
        cudaStreamCreateWithFlags(&sB, cudaStreamNonBlocking);
        cudaEventCreateWithFlags(&evF, cudaEventDisableTiming);
        cudaEventCreateWithFlags(&evJ, cudaEventDisableTiming);
    }

    // ---- fork: GEMM chain (stream sB) runs concurrently with edge chain (legacy) ----
    cudaEventRecord(evF, 0);
    cudaStreamWaitEvent(sB, evF, 0);

    // stream sB: pack W1 -> GEMM1 (depends only on x, W1)
    k_w1p<<<256, 256, 0, sB>>>(W1);
    dim3 g1(2, (n + 127) / 128);
    k_gemm1_h<<<g1, 256, 0, sB>>>(x, n);
    cudaEventRecord(evJ, sB);

    // legacy stream: edge chain
    k_prepA  <<<nbI + 20, 256>>>(n, nbI, W2);
    k_detect <<<64, 256>>>((const long long*)ei, E, n);
    k_convert<<<2048, 256>>>(ei, E, n);
    k_dinv   <<<nbI, 256>>>(n);
    k_scan1  <<<nb, 1024>>>(n);
    k_scan2  <<<1, 256>>>(nb);
    k_scan3  <<<nbI, 256>>>(n, E);
    k_fill   <<<2048, 256>>>(E);

    // ---- join: agg1 needs both chains ----
    cudaStreamWaitEvent(0, evJ, 0);
    int gAgg = min(3125, (n + 15) / 16);
    k_agg1<<<gAgg, 256>>>(b1, n);
    k_agg2<<<2048, 256>>>(b2, outF, outL, n, writeL);
}

// round 16
// speedup vs baseline: 1.7023x; 1.1907x over previous
#include <cuda_runtime.h>
#include <cuda_bf16.h>
#include <cuda_fp16.h>
#include <stdint.h>
#include <math.h>

// Problem constants (fixed by the reference)
#define F_IN   512
#define F_HID  256
#define F_OUT  40
#define MAXN   100000
#define MAXE   3200000

// ---------------- scratch (device globals; no runtime allocation) ----------------
__device__ int   g_is32;
__device__ int   g_eidx[2 * MAXE];
__device__ int   g_deg[MAXN];
__device__ int   g_cnt[MAXN];
__device__ float g_dinv[MAXN];
__device__ int   g_rowptr[MAXN + 1];
__device__ int   g_cursor[MAXN];
__device__ int   g_adj[MAXE];
__device__ int   g_part[256];
__device__ unsigned g_w2h[F_OUT * (F_HID / 2)];   // W2^T packed half2: [o][f2]
__device__ unsigned g_w1p[(F_IN / 2) * F_HID];    // W1 packed half2 along k: [k2][n]
__device__ unsigned g_hh[(long)MAXN * (F_HID/2)]; // h half2-packed (x@W1, UNSCALED)
__device__ float g_h2[(long)MAXN * F_OUT];        // h2_s = dinv[i] * (relu(...) @ W2)

// ---------------- helpers ----------------
__device__ __forceinline__ unsigned packh2(float lo, float hi) {
    __half2 h = __floats2half2_rn(lo, hi);
    return *(unsigned*)&h;
}

// ---------------- prep A (edge-chain stream): init counters + pack W2 ----------------
// blocks [0, nbI): init; [nbI, nbI+20): w2h (40*128 = 5120 elems)
__global__ void k_prepA(int n, int nbI, const float* __restrict__ W2) {
    int b = blockIdx.x;
    int t = threadIdx.x;
    if (b < nbI) {
        int i = b * 256 + t;
        if (i < n) { g_deg[i] = 1; g_cnt[i] = 0; }
        if (b == 0 && t == 0) g_is32 = 0;
    } else {
        int idx = (b - nbI) * 256 + t;          // < 5120
        int o = idx >> 7, f2 = idx & 127;
        g_w2h[idx] = packh2(W2[(2 * f2) * F_OUT + o], W2[(2 * f2 + 1) * F_OUT + o]);
    }
}

// ---------------- prep B (gemm stream): pack W1 ----------------
__global__ void k_w1p(const float* __restrict__ W1) {
    int idx = blockIdx.x * blockDim.x + threadIdx.x;   // < 256*256
    int k2 = idx >> 8;
    int nn = idx & 255;
    g_w1p[idx] = packh2(W1[(2 * k2) * F_HID + nn], W1[(2 * k2 + 1) * F_HID + nn]);
}

// Sample first 64K int64 words: any out-of-range value => data is really int32.
__global__ void k_detect(const long long* __restrict__ ei, int E, int n) {
    int cnt = min(E, 1 << 16);
    int bad = 0;
    for (int e = blockIdx.x * blockDim.x + threadIdx.x; e < cnt; e += gridDim.x * blockDim.x) {
        long long v = ei[e];
        if (v < 0 || v >= n) bad = 1;
    }
    if (__syncthreads_or(bad)) {
        if (threadIdx.x == 0) g_is32 = 1;
    }
}

// convert raw -> int32 g_eidx, with fused degree histogram
__global__ void k_convert(const void* __restrict__ ei_raw, int E, int n) {
    int is32 = g_is32;
    const int*       e32 = (const int*)ei_raw;
    const long long* e64 = (const long long*)ei_raw;
    for (long e = blockIdx.x * blockDim.x + threadIdx.x; e < 2L * E; e += (long)gridDim.x * blockDim.x) {
        long long v = is32 ? (long long)e32[e] : e64[e];
        if (v < 0) v = 0;
        if (v >= n) v = n - 1;
        int vi = (int)v;
        g_eidx[e] = vi;
        if (e < E) atomicAdd(&g_cnt[vi], 1);   // row counts
        else       atomicAdd(&g_deg[vi], 1);   // col degrees
    }
}

__global__ void k_dinv(int n) {
    int i = blockIdx.x * blockDim.x + threadIdx.x;
    if (i < n) g_dinv[i] = rsqrtf((float)g_deg[i]);
}

// ---------------- CSR build ----------------
__global__ void k_scan1(int n) {
    __shared__ int s[1024];
    int tid = threadIdx.x;
    int idx = blockIdx.x * 1024 + tid;
    int v = (idx < n) ? g_cnt[idx] : 0;
    s[tid] = v;
    __syncthreads();
    for (int off = 1; off < 1024; off <<= 1) {
        int t = (tid >= off) ? s[tid - off] : 0;
        __syncthreads();
        s[tid] += t;
        __syncthreads();
    }
    if (idx < n) g_rowptr[idx] = s[tid] - v;
    if (tid == 1023) g_part[blockIdx.x] = s[1023];
}

__global__ void k_scan2(int nb) {
    __shared__ int s[256];
    int tid = threadIdx.x;
    int v = (tid < nb) ? g_part[tid] : 0;
    s[tid] = v;
    __syncthreads();
    for (int off = 1; off < 256; off <<= 1) {
        int t = (tid >= off) ? s[tid - off] : 0;
        __syncthreads();
        s[tid] += t;
        __syncthreads();
    }
    if (tid < nb) g_part[tid] = s[tid] - v;
}

__global__ void k_scan3(int n, int E) {
    int i = blockIdx.x * blockDim.x + threadIdx.x;
    if (i < n) {
        int rp = g_rowptr[i] + g_part[i >> 10];
        g_rowptr[i] = rp;
        g_cursor[i] = rp;
    }
    if (blockIdx.x == 0 && threadIdx.x == 0) g_rowptr[n] = E;
}

__global__ void k_fill(int E) {
    for (int e = blockIdx.x * blockDim.x + threadIdx.x; e < E; e += gridDim.x * blockDim.x) {
        int r = g_eidx[e];
        int c = g_eidx[E + e];
        int pos = atomicAdd(&g_cursor[r], 1);
        g_adj[pos] = c;
    }
}

// ---------------- fp16 tensor-core GEMM1 (mma.sync.m16n8k16), NO dinv scaling ----------------
__device__ __forceinline__ void mma16(float c[4], const unsigned a[4], const unsigned b[2]) {
    asm volatile(
        "mma.sync.aligned.m16n8k16.row.col.f32.f16.f16.f32 "
        "{%0,%1,%2,%3}, {%4,%5,%6,%7}, {%8,%9}, {%0,%1,%2,%3};"
        : "+f"(c[0]), "+f"(c[1]), "+f"(c[2]), "+f"(c[3])
        : "r"(a[0]), "r"(a[1]), "r"(a[2]), "r"(a[3]), "r"(b[0]), "r"(b[1]));
}

#define SPAD 136

__global__ __launch_bounds__(256, 2) void k_gemm1_h(const float* __restrict__ A, int M) {
    __shared__ unsigned As2[2][16][SPAD];
    __shared__ unsigned Bs2[2][16][SPAD];

    const int tid  = threadIdx.x;
    const int lane = tid & 31;
    const int wid  = tid >> 5;
    const int wm   = wid & 1;
    const int wn   = wid >> 1;
    const int bx   = blockIdx.x;
    const long mBase = (long)blockIdx.y * 128;

    const int  rowA = tid & 127;
    const int  kfA  = (tid >> 7) * 16;
    const int  k2A  = kfA >> 1;
    const long gRowA = mBase + rowA;
    const bool okA   = gRowA < M;
    const float* Ag  = A + gRowA * F_IN + kfA;

    const int krB  = tid >> 4;
    const int colB = (tid & 15) * 8;
    const unsigned* Wp = g_w1p + (long)bx * 128 + colB;

    float fa[16];
    uint4 ub0, ub1;

    if (okA) {
#pragma unroll
        for (int j = 0; j < 4; j++) *(float4*)&fa[j * 4] = *(const float4*)(Ag + j * 4);
    } else {
#pragma unroll
        for (int j = 0; j < 16; j++) fa[j] = 0.f;
    }
    ub0 = *(const uint4*)(Wp + (long)krB * F_HID);
    ub1 = *(const uint4*)(Wp + (long)krB * F_HID + 4);

#pragma unroll
    for (int j = 0; j < 8; j++) As2[0][k2A + j][rowA] = packh2(fa[2 * j], fa[2 * j + 1]);
    *(uint4*)&Bs2[0][krB][colB]     = ub0;
    *(uint4*)&Bs2[0][krB][colB + 4] = ub1;
    __syncthreads();

    float c[4][4][4];
#pragma unroll
    for (int mt = 0; mt < 4; mt++)
#pragma unroll
        for (int nt = 0; nt < 4; nt++)
#pragma unroll
            for (int q = 0; q < 4; q++) c[mt][nt][q] = 0.f;

    int cur = 0;
    const int NITER = F_IN / 32;
    for (int it = 0; it < NITER; ++it) {
        if (it + 1 < NITER) {
            int kf = (it + 1) * 32;
            if (okA) {
#pragma unroll
                for (int j = 0; j < 4; j++) *(float4*)&fa[j * 4] = *(const float4*)(Ag + kf + j * 4);
            }
            ub0 = *(const uint4*)(Wp + (long)(kf / 2 + krB) * F_HID);
            ub1 = *(const uint4*)(Wp + (long)(kf / 2 + krB) * F_HID + 4);
        }

#pragma unroll
        for (int kk = 0; kk < 16; kk += 8) {
            const int k2q = kk + (lane & 3);
            const int p   = lane >> 2;
            unsigned afr[4][4], bfr[4][2];
#pragma unroll
            for (int mt = 0; mt < 4; mt++) {
                int r = wm * 64 + mt * 16 + p;
                afr[mt][0] = As2[cur][k2q][r];
                afr[mt][1] = As2[cur][k2q][r + 8];
                afr[mt][2] = As2[cur][k2q + 4][r];
                afr[mt][3] = As2[cur][k2q + 4][r + 8];
            }
#pragma unroll
            for (int nt = 0; nt < 4; nt++) {
                int cc = wn * 32 + nt * 8 + p;
                bfr[nt][0] = Bs2[cur][k2q][cc];
                bfr[nt][1] = Bs2[cur][k2q + 4][cc];
            }
#pragma unroll
            for (int mt = 0; mt < 4; mt++)
#pragma unroll
                for (int nt = 0; nt < 4; nt++)
                    mma16(c[mt][nt], afr[mt], bfr[nt]);
        }

        if (it + 1 < NITER) {
            int nxt = cur ^ 1;
#pragma unroll
            for (int j = 0; j < 8; j++) As2[nxt][k2A + j][rowA] = packh2(fa[2 * j], fa[2 * j + 1]);
            *(uint4*)&Bs2[nxt][krB][colB]     = ub0;
            *(uint4*)&Bs2[nxt][krB][colB + 4] = ub1;
            __syncthreads();
            cur = nxt;
        }
    }

    const int p  = lane >> 2;
    const int q2 = (lane & 3) * 2;
#pragma unroll
    for (int mt = 0; mt < 4; mt++) {
        long r0 = mBase + wm * 64 + mt * 16 + p;
        long r1 = r0 + 8;
        if (r0 < M) {
#pragma unroll
            for (int nt = 0; nt < 4; nt++) {
                int col = bx * 128 + wn * 32 + nt * 8 + q2;
                g_hh[r0 * (F_HID/2) + (col >> 1)] = packh2(c[mt][nt][0], c[mt][nt][1]);
            }
        }
        if (r1 < M) {
#pragma unroll
            for (int nt = 0; nt < 4; nt++) {
                int col = bx * 128 + wn * 32 + nt * 8 + q2;
                g_hh[r1 * (F_HID/2) + (col >> 1)] = packh2(c[mt][nt][2], c[mt][nt][3]);
            }
        }
    }
}

// ---------------- agg1 + bias + relu + batched tensor-core GEMM2 ----------------
// Warp-per-node gather: each warp owns a whole node (lane covers features
// 8l..8l+7 via one LDG.128 per edge), fp32 accumulation, no per-node syncs.
// 16 nodes per batch (2 per warp), then one 16x40x256 mma.m16n8k16 pass
// (5 warps x 16 k-steps), dinv[i]-scaled writeback.
__global__ __launch_bounds__(256) void k_agg1(const float* __restrict__ b1, int n) {
    __shared__ unsigned sw2[40 * 132];     // W2 half2 [o][f2], padded rows
    __shared__ unsigned hsp[16 * 132];     // batch hs half2 [b][f2], padded rows
    const int tid  = threadIdx.x;
    const int lane = tid & 31;
    const int w    = tid >> 5;

    for (int idx = tid; idx < 40 * 128; idx += 256) {
        int row = idx >> 7, col = idx & 127;
        sw2[row * 132 + col] = g_w2h[idx];
    }
    // lane owns features 8l..8l+7
    float4 bA = *(const float4*)(b1 + 8 * lane);
    float4 bB = *(const float4*)(b1 + 8 * lane + 4);

    for (int i0 = blockIdx.x * 16; i0 < n; i0 += gridDim.x * 16) {
        __syncthreads();   // protect hsp (GEMM2 of previous batch done)
#pragma unroll
        for (int rep = 0; rep < 2; rep++) {
            int ib = rep * 8 + w;
            int i  = i0 + ib;
            if (i < n) {
                int start = g_rowptr[i], end = g_rowptr[i + 1];
                float dvi = g_dinv[i];

                float acc[8];
                {   // self-loop: dinv[i] * h[i]
                    uint4 u = *(const uint4*)(g_hh + (long)i * 128 + lane * 4);
                    float2 f0 = __half22float2(*(__half2*)&u.x);
                    float2 f1 = __half22float2(*(__half2*)&u.y);
                    float2 f2v = __half22float2(*(__half2*)&u.z);
                    float2 f3 = __half22float2(*(__half2*)&u.w);
                    acc[0] = dvi * f0.x; acc[1] = dvi * f0.y;
                    acc[2] = dvi * f1.x; acc[3] = dvi * f1.y;
                    acc[4] = dvi * f2v.x; acc[5] = dvi * f2v.y;
                    acc[6] = dvi * f3.x; acc[7] = dvi * f3.y;
                }
#pragma unroll 4
                for (int e = start; e < end; e++) {
                    int   j = g_adj[e];    // broadcast
                    float d = g_dinv[j];   // broadcast
                    uint4 u = *(const uint4*)(g_hh + (long)j * 128 + lane * 4);
                    float2 f0 = __half22float2(*(__half2*)&u.x);
                    float2 f1 = __half22float2(*(__half2*)&u.y);
                    float2 f2v = __half22float2(*(__half2*)&u.z);
                    float2 f3 = __half22float2(*(__half2*)&u.w);
                    acc[0] = fmaf(d, f0.x, acc[0]);  acc[1] = fmaf(d, f0.y, acc[1]);
                    acc[2] = fmaf(d, f1.x, acc[2]);  acc[3] = fmaf(d, f1.y, acc[3]);
                    acc[4] = fmaf(d, f2v.x, acc[4]); acc[5] = fmaf(d, f2v.y, acc[5]);
                    acc[6] = fmaf(d, f3.x, acc[6]);  acc[7] = fmaf(d, f3.y, acc[7]);
                }
                // bias + relu, pack to hsp row ib
                float h0 = fmaxf(fmaf(acc[0], dvi, bA.x), 0.f);
                float h1 = fmaxf(fmaf(acc[1], dvi, bA.y), 0.f);
                float h2 = fmaxf(fmaf(acc[2], dvi, bA.z), 0.f);
                float h3 = fmaxf(fmaf(acc[3], dvi, bA.w), 0.f);
                float h4 = fmaxf(fmaf(acc[4], dvi, bB.x), 0.f);
                float h5 = fmaxf(fmaf(acc[5], dvi, bB.y), 0.f);
                float h6 = fmaxf(fmaf(acc[6], dvi, bB.z), 0.f);
                float h7 = fmaxf(fmaf(acc[7], dvi, bB.w), 0.f);
                unsigned* hr = &hsp[ib * 132 + lane * 4];
                hr[0] = packh2(h0, h1);
                hr[1] = packh2(h2, h3);
                hr[2] = packh2(h4, h5);
                hr[3] = packh2(h6, h7);
            }
        }
        __syncthreads();

        // ---- batched GEMM2: C(16x40) = hs(16x256) @ W2 ----
        if (w < 5) {
            const int r = lane >> 2, q = lane & 3;
            float cc[4] = {0.f, 0.f, 0.f, 0.f};
#pragma unroll
            for (int ks = 0; ks < 16; ks++) {
                int kk2 = ks * 8;
                unsigned a[4], b[2];
                a[0] = hsp[r * 132 + kk2 + q];
                a[1] = hsp[(r + 8) * 132 + kk2 + q];
                a[2] = hsp[r * 132 + kk2 + 4 + q];
                a[3] = hsp[(r + 8) * 132 + kk2 + 4 + q];
                b[0] = sw2[(w * 8 + r) * 132 + kk2 + q];
                b[1] = sw2[(w * 8 + r) * 132 + kk2 + 4 + q];
                mma16(cc, a, b);
            }
            long n0 = (long)i0 + r;
            long n1 = n0 + 8;
            int  o  = w * 8 + q * 2;
            if (n0 < n) {
                float dv = g_dinv[n0];
                *(float2*)(g_h2 + n0 * F_OUT + o) = make_float2(cc[0] * dv, cc[1] * dv);
            }
            if (n1 < n) {
                float dv = g_dinv[n1];
                *(float2*)(g_h2 + n1 * F_OUT + o) = make_float2(cc[2] * dv, cc[3] * dv);
            }
        }
    }
}

// ---------------- agg2 + bias + log_softmax (dual accumulator chains) ----------------
__global__ __launch_bounds__(256) void k_agg2(const float* __restrict__ b2,
                                              float* __restrict__ outF,
                                              float* __restrict__ outL,
                                              int n, int writeL) {
    int lane = threadIdx.x & 31;
    int wid  = (blockIdx.x * blockDim.x + threadIdx.x) >> 5;
    int nw   = (gridDim.x * blockDim.x) >> 5;
    float bias0 = b2[lane];
    float bias1 = (lane < 8) ? b2[32 + lane] : 0.f;

    for (int i = wid; i < n; i += nw) {
        int start = g_rowptr[i];
        int end   = g_rowptr[i + 1];
        long ib = (long)i * F_OUT;
        float a0 = g_h2[ib + lane];
        float a1 = (lane < 8) ? g_h2[ib + 32 + lane] : 0.f;
        float c0 = 0.f, c1 = 0.f;   // second independent chain
        int e = start;
        for (; e + 1 < end; e += 2) {
            int j0 = g_adj[e];
            int j1 = g_adj[e + 1];
            long jb0 = (long)j0 * F_OUT;
            long jb1 = (long)j1 * F_OUT;
            a0 += g_h2[jb0 + lane];
            c0 += g_h2[jb1 + lane];
            if (lane < 8) {
                a1 += g_h2[jb0 + 32 + lane];
                c1 += g_h2[jb1 + 32 + lane];
            }
        }
        if (e < end) {
            long jb = (long)g_adj[e] * F_OUT;
            a0 += g_h2[jb + lane];
            if (lane < 8) a1 += g_h2[jb + 32 + lane];
        }
        a0 += c0; a1 += c1;

        float dv = g_dinv[i];
        float f0 = fmaf(a0, dv, bias0);
        float f1 = (lane < 8) ? fmaf(a1, dv, bias1) : -INFINITY;
        outF[ib + lane] = f0;
        if (lane < 8) outF[ib + 32 + lane] = f1;

        if (writeL) {
            float mx = fmaxf(f0, f1);
#pragma unroll
            for (int off = 16; off; off >>= 1)
                mx = fmaxf(mx, __shfl_xor_sync(0xffffffffu, mx, off));
            float s = expf(f0 - mx) + ((lane < 8) ? expf(f1 - mx) : 0.f);
#pragma unroll
            for (int off = 16; off; off >>= 1)
                s += __shfl_xor_sync(0xffffffffu, s, off);
            float lse = mx + logf(s);
            outL[ib + lane] = f0 - lse;
            if (lane < 8) outL[ib + 32 + lane] = f1 - lse;
        }
    }
}

// ---------------- launch ----------------
extern "C" void kernel_launch(void* const* d_in, const int* in_sizes, int n_in,
                              void* d_out, int out_size) {
    const float* x  = (const float*)d_in[0];
    const void*  ei = d_in[1];
    const float* W1 = (const float*)d_in[2];
    const float* b1 = (const float*)d_in[3];
    const float* W2 = (const float*)d_in[4];
    const float* b2 = (const float*)d_in[5];

    int n = in_sizes[0] / F_IN;
    int E = in_sizes[1] / 2;

    float* out = (float*)d_out;
    int half = n * F_OUT;
    float* outF = out;
    float* outL = out;
    int writeL = 0;
    if (out_size >= 2 * half) { outL = out + half; writeL = 1; }

    int nb  = (n + 1023) >> 10;
    int nbI = (n + 255) / 256;

    // One-time stream/event creation (happens on the correctness call, which
    // precedes graph capture; identical GPU work is issued on every call).
    static cudaStream_t sB = 0;
    static cudaEvent_t  evF = 0, evJ = 0;
    if (!sB) {
        cudaStreamCreateWithFlags(&sB, cudaStreamNonBlocking);
        cudaEventCreateWithFlags(&evF, cudaEventDisableTiming);
        cudaEventCreateWithFlags(&evJ, cudaEventDisableTiming);
    }

    // ---- fork: GEMM chain (stream sB) runs concurrently with edge chain (legacy) ----
    cudaEventRecord(evF, 0);
    cudaStreamWaitEvent(sB, evF, 0);

    // stream sB: pack W1 -> GEMM1 (depends only on x, W1)
    k_w1p<<<256, 256, 0, sB>>>(W1);
    dim3 g1(2, (n + 127) / 128);
    k_gemm1_h<<<g1, 256, 0, sB>>>(x, n);
    cudaEventRecord(evJ, sB);

    // legacy stream: edge chain
    k_prepA  <<<nbI + 20, 256>>>(n, nbI, W2);
    k_detect <<<64, 256>>>((const long long*)ei, E, n);
    k_convert<<<2048, 256>>>(ei, E, n);
    k_dinv   <<<nbI, 256>>>(n);
    k_scan1  <<<nb, 1024>>>(n);
    k_scan2  <<<1, 256>>>(nb);
    k_scan3  <<<nbI, 256>>>(n, E);
    k_fill   <<<2048, 256>>>(E);

    // ---- join: agg1 needs both chains ----
    cudaStreamWaitEvent(0, evJ, 0);
    int gAgg = (n + 15) / 16;
    k_agg1<<<gAgg, 256>>>(b1, n);
    k_agg2<<<2048, 256>>>(b2, outF, outL, n, writeL);
}